// round 15
// baseline (speedup 1.0000x reference)
#include <cuda_runtime.h>
#include <cuda_bf16.h>
#include <cstdint>

// ---------------- problem constants ----------------
#define BB 64
#define NN 8192
#define PP 8
#define SS 1024
#define MM 8
#define KK 7
#define NPATCH (BB*PP)   // 512

// ---------------- device scratch (no allocations allowed) ----------------
__device__ float g_seed[NPATCH * 3];
__device__ float g_patch[NPATCH * 3 * SS];      // normalized patch coords, SoA [bp][c][s]
__device__ float g_mean[NPATCH * 3];
__device__ float g_norm[NPATCH];
__device__ float g_feat[NPATCH * 128];          // maxpool accumulator (atomicMax on bits)

// smem/global weight-buffer layout (bytes)
#define O_W1H 0
#define O_W1L 3072
#define O_W2H 6144
#define O_W2L 15360
#define O_W3H 24576
#define O_W3L 33792
#define O_W4H 43008
#define O_W4L 61440
#define O_W5H 79872
#define O_W5L 114688
#define O_BIAS 149504        // 448 floats: b1@0 b2@64 b3@128 b4@192 b5@320
#define DYN_TOT 151296

__device__ __align__(16) unsigned char g_wbuf[DYN_TOT];

// =========================================================================
// helpers
// =========================================================================
__device__ __forceinline__ uint32_t smem_to_u32(const void* smem_ptr) {
    uint32_t addr;
    asm("{ .reg .u64 tmp; cvta.to.shared.u64 tmp, %1; cvt.u32.u64 %0, tmp; }"
        : "=r"(addr) : "l"(smem_ptr));
    return addr;
}

__device__ __forceinline__ void mma_bf16(float* c, const uint32_t* a, uint32_t b0, uint32_t b1) {
    asm volatile(
        "mma.sync.aligned.m16n8k16.row.col.f32.bf16.bf16.f32 "
        "{%0,%1,%2,%3}, {%4,%5,%6,%7}, {%8,%9}, {%0,%1,%2,%3};"
        : "+f"(c[0]), "+f"(c[1]), "+f"(c[2]), "+f"(c[3])
        : "r"(a[0]), "r"(a[1]), "r"(a[2]), "r"(a[3]), "r"(b0), "r"(b1));
}

__device__ __forceinline__ void ldm_x2(uint32_t& r0, uint32_t& r1, uint32_t addr) {
    asm volatile("ldmatrix.sync.aligned.m8n8.x2.shared.b16 {%0,%1}, [%2];"
                 : "=r"(r0), "=r"(r1) : "r"(addr));
}

// split (f0 -> low half, f1 -> high half) into hi/lo bf16x2 words.
__device__ __forceinline__ void split2(float f0, float f1, uint32_t& hi, uint32_t& lo) {
    uint32_t h, l;
    asm("cvt.rn.bf16x2.f32 %0, %1, %2;" : "=r"(h) : "f"(f1), "f"(f0));
    float r1 = __uint_as_float(h & 0xFFFF0000u);
    float r0 = __uint_as_float(h << 16);
    float d1 = f1 - r1;
    float d0 = f0 - r0;
    asm("cvt.rn.bf16x2.f32 %0, %1, %2;" : "=r"(l) : "f"(d1), "f"(d0));
    hi = h; lo = l;
}

// =========================================================================
// Kernel 1: farthest point sampling + uniform weight-prep tail.
// All 64 blocks: FPS for their batch, then 1/64 of the weight staging.
// =========================================================================
template<int K, int N, int STRIDE>
__device__ __forceinline__ void stage_wg(const float* __restrict__ w,
                                         char* hi, char* lo, int t, int nt) {
    for (int i = t; i < K * N; i += nt) {
        int k = i / N, n = i - k * N;
        float f = w[i];
        __nv_bfloat16 h = __float2bfloat16(f);
        __nv_bfloat16 l = __float2bfloat16(f - __bfloat162float(h));
        int off = n * STRIDE + k * 2;
        *(__nv_bfloat16*)(hi + off) = h;
        *(__nv_bfloat16*)(lo + off) = l;
    }
}

__global__ void fps_prep_kernel(
    const float* __restrict__ xyz,
    const float* __restrict__ mw0, const float* __restrict__ mb0,
    const float* __restrict__ mw1, const float* __restrict__ mb1,
    const float* __restrict__ mw2, const float* __restrict__ mb2,
    const float* __restrict__ mw3, const float* __restrict__ mb3,
    const float* __restrict__ mw4, const float* __restrict__ mb4) {
    int b = blockIdx.x;
    const float* X = xyz + (size_t)b * 3 * NN;
    __shared__ float s_v[32];
    __shared__ int   s_i[32];
    __shared__ float s_c[3];
    __shared__ int   s_far;
    int tid = threadIdx.x;
    int lane = tid & 31;
    int wrp = tid >> 5;

    float cxr[8], cyr[8], czr[8], dist[8];
#pragma unroll
    for (int k = 0; k < 8; k++) {
        int i = tid + k * 1024;
        cxr[k] = X[i]; cyr[k] = X[NN + i]; czr[k] = X[2 * NN + i];
        dist[k] = 1e10f;
    }
    int far = 0;

    for (int it = 0; it < PP; it++) {
        if (tid == 0) {
            float fx = X[far], fy = X[NN + far], fz = X[2 * NN + far];
            s_c[0] = fx; s_c[1] = fy; s_c[2] = fz;
            g_seed[(b * PP + it) * 3 + 0] = fx;
            g_seed[(b * PP + it) * 3 + 1] = fy;
            g_seed[(b * PP + it) * 3 + 2] = fz;
        }
        __syncthreads();
        float cx = s_c[0], cy = s_c[1], cz = s_c[2];
        float bv = -1.0f; int bi = 0;
#pragma unroll
        for (int k = 0; k < 8; k++) {
            int i = tid + k * 1024;
            float dx = cxr[k] - cx, dy = cyr[k] - cy, dz = czr[k] - cz;
            float d = dx * dx + dy * dy + dz * dz;
            float nd = fminf(dist[k], d);
            dist[k] = nd;
            if (nd > bv || (nd == bv && i < bi)) { bv = nd; bi = i; }
        }
#pragma unroll
        for (int o = 16; o > 0; o >>= 1) {
            float ov = __shfl_xor_sync(0xffffffffu, bv, o);
            int oi = __shfl_xor_sync(0xffffffffu, bi, o);
            if (ov > bv || (ov == bv && oi < bi)) { bv = ov; bi = oi; }
        }
        if (lane == 0) { s_v[wrp] = bv; s_i[wrp] = bi; }
        __syncthreads();
        if (wrp == 0) {
            float mv = s_v[lane]; int mi = s_i[lane];
#pragma unroll
            for (int o = 16; o > 0; o >>= 1) {
                float ov = __shfl_xor_sync(0xffffffffu, mv, o);
                int oi = __shfl_xor_sync(0xffffffffu, mi, o);
                if (ov > mv || (ov == mv && oi < mi)) { mv = ov; mi = oi; }
            }
            if (lane == 0) s_far = mi;
        }
        __syncthreads();
        far = s_far;
        __syncthreads();
    }

    // ---- uniform weight-prep tail: block b stages its 1/64 share ----
    {
        int t = b * 1024 + tid;
        int nt = BB * 1024;
        char* B = (char*)g_wbuf;
        for (int i = t; i < 64 * 16; i += nt) {
            int n = i >> 4, k = i & 15;
            float f = (k < 3) ? mw0[k * 64 + n] : 0.f;
            __nv_bfloat16 h = __float2bfloat16(f);
            __nv_bfloat16 l = __float2bfloat16(f - __bfloat162float(h));
            int off = n * 48 + k * 2;
            *(__nv_bfloat16*)(B + O_W1H + off) = h;
            *(__nv_bfloat16*)(B + O_W1L + off) = l;
        }
        stage_wg<64, 64, 144>(mw1, B + O_W2H, B + O_W2L, t, nt);
        stage_wg<64, 64, 144>(mw2, B + O_W3H, B + O_W3L, t, nt);
        stage_wg<64, 128, 144>(mw3, B + O_W4H, B + O_W4L, t, nt);
        stage_wg<128, 128, 272>(mw4, B + O_W5H, B + O_W5L, t, nt);
        float* bias = (float*)(B + O_BIAS);
        for (int i = t; i < 64; i += nt) {
            bias[i] = mb0[i]; bias[64 + i] = mb1[i]; bias[128 + i] = mb2[i];
        }
        for (int i = t; i < 128; i += nt) {
            bias[192 + i] = mb3[i]; bias[320 + i] = mb4[i];
        }
    }
}

// =========================================================================
// Kernel 2: KNN radix-select + patch normalization.
// Identical histogram/selection; reductions via two-stage shuffles.
// =========================================================================
__global__ void __launch_bounds__(512) knn_kernel(const float* __restrict__ xyz) {
    int bp = blockIdx.x;
    int b = bp >> 3;
    const float* X = xyz + (size_t)b * 3 * NN;
    __shared__ unsigned s_key[NN];
    __shared__ int s_sel[SS];
    __shared__ int s_hist[512];
    __shared__ unsigned s_pref;
    __shared__ int s_kk;
    __shared__ int s_cnt[2];
    __shared__ float s_red[80];
    int tid = threadIdx.x;
    int lane = tid & 31;
    int wrp = tid >> 5;                   // 0..15

    if (tid < 128) g_feat[bp * 128 + tid] = 0.f;

    float sx = g_seed[bp * 3 + 0], sy = g_seed[bp * 3 + 1], sz = g_seed[bp * 3 + 2];
    float s2 = sx * sx + sy * sy + sz * sz;

    for (int i = tid; i < NN; i += 512) {
        float px = X[i], py = X[NN + i], pz = X[2 * NN + i];
        float p2 = px * px + py * py + pz * pz;
        float dot = sx * px + sy * py + sz * pz;
        float d = (s2 - 2.0f * dot) + p2;
        unsigned u = __float_as_uint(d);
        u = (u & 0x80000000u) ? ~u : (u | 0x80000000u);
        s_key[i] = u;
    }
    if (tid == 0) { s_pref = 0u; s_kk = SS; }
    __syncthreads();

    unsigned prefix = 0, maskHi = 0;
    int bank = ((tid >> 5) & 1) * 256;
    for (int pass = 0; pass < 4; pass++) {
        int shift = 24 - 8 * pass;
        s_hist[tid] = 0;
        __syncthreads();
        for (int i = tid; i < NN; i += 512) {
            unsigned u = s_key[i];
            if ((u & maskHi) == prefix) atomicAdd(&s_hist[bank + ((u >> shift) & 255)], 1);
        }
        __syncthreads();
        if (tid < 32) {
            int kk = s_kk;
            unsigned pref = s_pref;
            int sv[8]; int tot = 0;
#pragma unroll
            for (int j = 0; j < 8; j++) {
                int v = s_hist[lane * 8 + j] + s_hist[256 + lane * 8 + j];
                sv[j] = v; tot += v;
            }
            int run = tot;
#pragma unroll
            for (int o = 1; o < 32; o <<= 1) {
                int v = __shfl_up_sync(0xffffffffu, run, o);
                if (lane >= o) run += v;
            }
            int excl = run - tot;
            if (kk > excl && kk <= run) {
                int cum = excl;
#pragma unroll
                for (int j = 0; j < 8; j++) {
                    if (cum + sv[j] >= kk) {
                        s_pref = pref | ((unsigned)(lane * 8 + j) << shift);
                        s_kk = kk - cum;
                        break;
                    }
                    cum += sv[j];
                }
            }
        }
        __syncthreads();
        prefix = s_pref;
        maskHi |= (0xFFu << shift);
        __syncthreads();
    }
    unsigned T = prefix;

    if (tid == 0) { s_cnt[0] = 0; s_cnt[1] = 0; }
    __syncthreads();
    for (int i = tid; i < NN; i += 512) {
        bool pred = s_key[i] < T;
        unsigned m = __ballot_sync(0xffffffffu, pred);
        int cnt = __popc(m);
        int base = 0;
        if (lane == 0 && cnt) base = atomicAdd(&s_cnt[0], cnt);
        base = __shfl_sync(0xffffffffu, base, 0);
        if (pred) s_sel[base + __popc(m & ((1u << lane) - 1u))] = i;
    }
    __syncthreads();
    int nLess = s_cnt[0];
    for (int i = tid; i < NN; i += 512) {
        bool pred = s_key[i] == T;
        unsigned m = __ballot_sync(0xffffffffu, pred);
        int cnt = __popc(m);
        int base = 0;
        if (lane == 0 && cnt) base = atomicAdd(&s_cnt[1], cnt);
        base = __shfl_sync(0xffffffffu, base, 0);
        if (pred) {
            int pos = nLess + base + __popc(m & ((1u << lane) - 1u));
            if (pos < SS) s_sel[pos] = i;
        }
    }
    __syncthreads();

    float* cxs = (float*)s_key;
    float* cys = cxs + SS;
    float* czs = cxs + 2 * SS;
    float ax = 0.f, ay = 0.f, az = 0.f;
    for (int j = tid; j < SS; j += 512) {
        int i = s_sel[j];
        float px = X[i], py = X[NN + i], pz = X[2 * NN + i];
        cxs[j] = px; cys[j] = py; czs[j] = pz;
        ax += px; ay += py; az += pz;
    }
    // --- two-stage shuffle reduction for the 3 sums ---
#pragma unroll
    for (int o = 16; o > 0; o >>= 1) {
        ax += __shfl_xor_sync(0xffffffffu, ax, o);
        ay += __shfl_xor_sync(0xffffffffu, ay, o);
        az += __shfl_xor_sync(0xffffffffu, az, o);
    }
    if (lane == 0) { s_red[wrp] = ax; s_red[16 + wrp] = ay; s_red[32 + wrp] = az; }
    __syncthreads();
    if (wrp == 0) {
        // lanes 0-15 reduce x partials, lanes 16-31 reduce y partials
        float v = s_red[lane];        // [0..15]=x, [16..31]=y
#pragma unroll
        for (int o = 8; o > 0; o >>= 1) v += __shfl_xor_sync(0xffffffffu, v, o);
        if (lane == 0) s_red[64] = v;
        if (lane == 16) s_red[65] = v;
    } else if (wrp == 1) {
        float v = (lane < 16) ? s_red[32 + lane] : 0.f;
#pragma unroll
        for (int o = 8; o > 0; o >>= 1) v += __shfl_xor_sync(0xffffffffu, v, o);
        if (lane == 0) s_red[66] = v;
    }
    __syncthreads();
    float mx = s_red[64] * (1.0f / SS);
    float my = s_red[65] * (1.0f / SS);
    float mz = s_red[66] * (1.0f / SS);

    // --- max L2 norm (two-stage shuffle max) ---
    float mnorm = 0.f;
    for (int j = tid; j < SS; j += 512) {
        float dx = cxs[j] - mx, dy = cys[j] - my, dz = czs[j] - mz;
        float l = sqrtf(dx * dx + dy * dy + dz * dz);
        mnorm = fmaxf(mnorm, l);
    }
#pragma unroll
    for (int o = 16; o > 0; o >>= 1)
        mnorm = fmaxf(mnorm, __shfl_xor_sync(0xffffffffu, mnorm, o));
    if (lane == 0) s_red[wrp] = mnorm;
    __syncthreads();
    if (wrp == 0) {
        float v = (lane < 16) ? s_red[lane] : 0.f;
#pragma unroll
        for (int o = 8; o > 0; o >>= 1) v = fmaxf(v, __shfl_xor_sync(0xffffffffu, v, o));
        if (lane == 0) s_red[64] = v;
    }
    __syncthreads();
    float nrm = s_red[64];

    for (int j = tid; j < SS; j += 512) {
        g_patch[(bp * 3 + 0) * SS + j] = (cxs[j] - mx) / nrm;
        g_patch[(bp * 3 + 1) * SS + j] = (cys[j] - my) / nrm;
        g_patch[(bp * 3 + 2) * SS + j] = (czs[j] - mz) / nrm;
    }
    if (tid == 0) {
        g_mean[bp * 3 + 0] = mx; g_mean[bp * 3 + 1] = my; g_mean[bp * 3 + 2] = mz;
        g_norm[bp] = nrm;
    }
}

// =========================================================================
// Kernel 3: fused MLP — EXACT Round-9 configuration (best measured: 263.3us).
// =========================================================================
template<int KC, int NT, int STRIDE>
__device__ __forceinline__ void layer_forward2(
    const uint32_t (*Ah0)[4], const uint32_t (*Al0)[4],
    const uint32_t (*Ah1)[4], const uint32_t (*Al1)[4],
    uint32_t wH, uint32_t wL, const float* __restrict__ bias, int lane,
    uint32_t (*Oh0)[4], uint32_t (*Ol0)[4],
    uint32_t (*Oh1)[4], uint32_t (*Ol1)[4]) {
    uint32_t lm = (uint32_t)(lane & 7) * STRIDE + (uint32_t)((lane >> 3) & 1) * 16;
    int t4 = lane & 3;
#pragma unroll
    for (int np = 0; np < NT / 2; np++) {
        float ccA[2][4], ccB[2][4];
#pragma unroll
        for (int sub = 0; sub < 2; sub++) {
            int nt = np * 2 + sub;
            uint32_t ro = lm + (uint32_t)nt * 8u * STRIDE;
            float c1a[4] = {0.f, 0.f, 0.f, 0.f}, c2a[4] = {0.f, 0.f, 0.f, 0.f};
            float c1b[4] = {0.f, 0.f, 0.f, 0.f}, c2b[4] = {0.f, 0.f, 0.f, 0.f};
#pragma unroll
            for (int kc = 0; kc < KC; kc++) {
                uint32_t b0, b1, l0, l1;
                ldm_x2(b0, b1, wH + ro + kc * 32);
                ldm_x2(l0, l1, wL + ro + kc * 32);
                mma_bf16(c1a, Ah0[kc], b0, b1);
                mma_bf16(c1b, Ah1[kc], b0, b1);
                mma_bf16(c2a, Ah0[kc], l0, l1);
                mma_bf16(c2b, Ah1[kc], l0, l1);
                mma_bf16(c2a, Al0[kc], b0, b1);
                mma_bf16(c2b, Al1[kc], b0, b1);
            }
            float2 bb = *reinterpret_cast<const float2*>(bias + nt * 8 + t4 * 2);
            ccA[sub][0] = fmaxf(c1a[0] + c2a[0] + bb.x, 0.f);
            ccA[sub][1] = fmaxf(c1a[1] + c2a[1] + bb.y, 0.f);
            ccA[sub][2] = fmaxf(c1a[2] + c2a[2] + bb.x, 0.f);
            ccA[sub][3] = fmaxf(c1a[3] + c2a[3] + bb.y, 0.f);
            ccB[sub][0] = fmaxf(c1b[0] + c2b[0] + bb.x, 0.f);
            ccB[sub][1] = fmaxf(c1b[1] + c2b[1] + bb.y, 0.f);
            ccB[sub][2] = fmaxf(c1b[2] + c2b[2] + bb.x, 0.f);
            ccB[sub][3] = fmaxf(c1b[3] + c2b[3] + bb.y, 0.f);
        }
        split2(ccA[0][0], ccA[0][1], Oh0[np][0], Ol0[np][0]);
        split2(ccA[0][2], ccA[0][3], Oh0[np][1], Ol0[np][1]);
        split2(ccA[1][0], ccA[1][1], Oh0[np][2], Ol0[np][2]);
        split2(ccA[1][2], ccA[1][3], Oh0[np][3], Ol0[np][3]);
        split2(ccB[0][0], ccB[0][1], Oh1[np][0], Ol1[np][0]);
        split2(ccB[0][2], ccB[0][3], Oh1[np][1], Ol1[np][1]);
        split2(ccB[1][0], ccB[1][1], Oh1[np][2], Ol1[np][2]);
        split2(ccB[1][2], ccB[1][3], Oh1[np][3], Ol1[np][3]);
    }
}

template<int KC, int NT, int STRIDE>
__device__ __forceinline__ void layer_final2(
    const uint32_t (*Ah0)[4], const uint32_t (*Al0)[4],
    const uint32_t (*Ah1)[4], const uint32_t (*Al1)[4],
    uint32_t wH, uint32_t wL, const float* __restrict__ bias, int lane, int* smax) {
    uint32_t lm = (uint32_t)(lane & 7) * STRIDE + (uint32_t)((lane >> 3) & 1) * 16;
    int t4 = lane & 3;
#pragma unroll
    for (int nt = 0; nt < NT; nt++) {
        uint32_t ro = lm + (uint32_t)nt * 8u * STRIDE;
        float c1a[4] = {0.f, 0.f, 0.f, 0.f}, c2a[4] = {0.f, 0.f, 0.f, 0.f};
        float c1b[4] = {0.f, 0.f, 0.f, 0.f}, c2b[4] = {0.f, 0.f, 0.f, 0.f};
#pragma unroll
        for (int kc = 0; kc < KC; kc++) {
            uint32_t b0, b1, l0, l1;
            ldm_x2(b0, b1, wH + ro + kc * 32);
            ldm_x2(l0, l1, wL + ro + kc * 32);
            mma_bf16(c1a, Ah0[kc], b0, b1);
            mma_bf16(c1b, Ah1[kc], b0, b1);
            mma_bf16(c2a, Ah0[kc], l0, l1);
            mma_bf16(c2b, Ah1[kc], l0, l1);
            mma_bf16(c2a, Al0[kc], b0, b1);
            mma_bf16(c2b, Al1[kc], b0, b1);
        }
        float2 bb = *reinterpret_cast<const float2*>(bias + nt * 8 + t4 * 2);
        float v0a = fmaxf(c1a[0] + c2a[0] + bb.x, 0.f), v2a = fmaxf(c1a[2] + c2a[2] + bb.x, 0.f);
        float v1a = fmaxf(c1a[1] + c2a[1] + bb.y, 0.f), v3a = fmaxf(c1a[3] + c2a[3] + bb.y, 0.f);
        float v0b = fmaxf(c1b[0] + c2b[0] + bb.x, 0.f), v2b = fmaxf(c1b[2] + c2b[2] + bb.x, 0.f);
        float v1b = fmaxf(c1b[1] + c2b[1] + bb.y, 0.f), v3b = fmaxf(c1b[3] + c2b[3] + bb.y, 0.f);
        float m0 = fmaxf(fmaxf(v0a, v2a), fmaxf(v0b, v2b));
        float m1 = fmaxf(fmaxf(v1a, v3a), fmaxf(v1b, v3b));
#pragma unroll
        for (int off = 4; off < 32; off <<= 1) {
            m0 = fmaxf(m0, __shfl_xor_sync(0xffffffffu, m0, off));
            m1 = fmaxf(m1, __shfl_xor_sync(0xffffffffu, m1, off));
        }
        if (lane < 4) {
            atomicMax(&smax[nt * 8 + 2 * lane], __float_as_int(m0));
            atomicMax(&smax[nt * 8 + 2 * lane + 1], __float_as_int(m1));
        }
    }
}

__global__ void __launch_bounds__(256, 1) mlp_mma_kernel() {
    extern __shared__ char sm[];
    __shared__ int smax[128];
    int bp2 = blockIdx.x;
    int bp = bp2 >> 1;
    int half = bp2 & 1;
    int tid = threadIdx.x;
    int lane = tid & 31;
    int w = tid >> 5;
    uint32_t sbase = smem_to_u32(sm);

    if (tid < 128) smax[tid] = 0;
    {
        const uint4* src = (const uint4*)g_wbuf;
        uint4* dst = (uint4*)sm;
        for (int i = tid; i < DYN_TOT / 16; i += 256) dst[i] = src[i];
    }
    __syncthreads();

    const float* sbias = (const float*)(sm + O_BIAS);
    const float* PX = &g_patch[(bp * 3 + 0) * SS];
    const float* PY = &g_patch[(bp * 3 + 1) * SS];
    const float* PZ = &g_patch[(bp * 3 + 2) * SS];
    int t4 = lane & 3;

    for (int it = 0; it < 2; it++) {
        int pbase = half * 512 + it * 256 + w * 32 + (lane >> 2);
        float x0 = PX[pbase], y0 = PY[pbase], z0 = PZ[pbase];
        float x1 = PX[pbase + 8], y1 = PY[pbase + 8], z1 = PZ[pbase + 8];
        float x2 = PX[pbase + 16], y2 = PY[pbase + 16], z2 = PZ[pbase + 16];
        float x3 = PX[pbase + 24], y3 = PY[pbase + 24], z3 = PZ[pbase + 24];

        uint32_t A1h0[1][4] = {{0u, 0u, 0u, 0u}}, A1l0[1][4] = {{0u, 0u, 0u, 0u}};
        uint32_t A1h1[1][4] = {{0u, 0u, 0u, 0u}}, A1l1[1][4] = {{0u, 0u, 0u, 0u}};
        if (t4 == 0) {
            split2(x0, y0, A1h0[0][0], A1l0[0][0]);
            split2(x1, y1, A1h0[0][1], A1l0[0][1]);
            split2(x2, y2, A1h1[0][0], A1l1[0][0]);
            split2(x3, y3, A1h1[0][1], A1l1[0][1]);
        } else if (t4 == 1) {
            split2(z0, 0.f, A1h0[0][0], A1l0[0][0]);
            split2(z1, 0.f, A1h0[0][1], A1l0[0][1]);
            split2(z2, 0.f, A1h1[0][0], A1l1[0][0]);
            split2(z3, 0.f, A1h1[0][1], A1l1[0][1]);
        }

        uint32_t A2h0[4][4], A2l0[4][4], A2h1[4][4], A2l1[4][4];
        uint32_t A3h0[4][4], A3l0[4][4], A3h1[4][4], A3l1[4][4];
        uint32_t A4h0[4][4], A4l0[4][4], A4h1[4][4], A4l1[4][4];
        uint32_t A5h0[8][4], A5l0[8][4], A5h1[8][4], A5l1[8][4];

        layer_forward2<1, 8, 48>(A1h0, A1l0, A1h1, A1l1,
            sbase + O_W1H, sbase + O_W1L, sbias + 0, lane,
            A2h0, A2l0, A2h1, A2l1);
        layer_forward2<4, 8, 144>(A2h0, A2l0, A2h1, A2l1,
            sbase + O_W2H, sbase + O_W2L, sbias + 64, lane,
            A3h0, A3l0, A3h1, A3l1);
        layer_forward2<4, 8, 144>(A3h0, A3l0, A3h1, A3l1,
            sbase + O_W3H, sbase + O_W3L, sbias + 128, lane,
            A4h0, A4l0, A4h1, A4l1);
        layer_forward2<4, 16, 144>(A4h0, A4l0, A4h1, A4l1,
            sbase + O_W4H, sbase + O_W4L, sbias + 192, lane,
            A5h0, A5l0, A5h1, A5l1);
        layer_final2<8, 16, 272>(A5h0, A5l0, A5h1, A5l1,
            sbase + O_W5H, sbase + O_W5L, sbias + 320, lane, smax);
    }
    __syncthreads();
    if (tid < 128) atomicMax((int*)&g_feat[bp * 128 + tid], smax[tid]);
}

// =========================================================================
// Kernel 4: FUSED FC decoder + SoftProjection (proven, round 14).
// =========================================================================
__global__ void __launch_bounds__(1024) dec_proj_kernel(
    const float* __restrict__ fw0, const float* __restrict__ fb0,
    const float* __restrict__ fw1, const float* __restrict__ fb1,
    const float* __restrict__ fw2, const float* __restrict__ fb2,
    const float* __restrict__ fw3, const float* __restrict__ fb3,
    const float* __restrict__ temperature,
    float* __restrict__ out) {
    int pbase = blockIdx.x * 4;
    int tid = threadIdx.x;
    int c = tid & 255;
    int q = tid >> 8;            // k-quarter 0..3
    __shared__ float sA[4][256];
    __shared__ float sB[4][256];
    __shared__ float sP[3][4][256];
    __shared__ float s_gen[4][24];

    if (tid < 512) {
        int p = tid >> 7, cc = tid & 127;
        sA[p][cc] = g_feat[(pbase + p) * 128 + cc];
    }
    __syncthreads();

    {
        float acc[4] = {0.f, 0.f, 0.f, 0.f};
        const float* W = fw0 + (q * 32) * 256 + c;
#pragma unroll 8
        for (int k = 0; k < 32; k++) {
            float wv = W[k * 256];
#pragma unroll
            for (int p = 0; p < 4; p++) acc[p] = fmaf(sA[p][q * 32 + k], wv, acc[p]);
        }
        if (q > 0) {
#pragma unroll
            for (int p = 0; p < 4; p++) sP[q - 1][p][c] = acc[p];
        }
        __syncthreads();
        if (q == 0) {
            float bv = fb0[c];
#pragma unroll
            for (int p = 0; p < 4; p++)
                sB[p][c] = fmaxf(acc[p] + sP[0][p][c] + sP[1][p][c] + sP[2][p][c] + bv, 0.f);
        }
        __syncthreads();
    }
    {
        float acc[4] = {0.f, 0.f, 0.f, 0.f};
        const float* W = fw1 + (q * 64) * 256 + c;
#pragma unroll 8
        for (int k = 0; k < 64; k++) {
            float wv = W[k * 256];
#pragma unroll
            for (int p = 0; p < 4; p++) acc[p] = fmaf(sB[p][q * 64 + k], wv, acc[p]);
        }
        if (q > 0) {
#pragma unroll
            for (int p = 0; p < 4; p++) sP[q - 1][p][c] = acc[p];
        }
        __syncthreads();
        if (q == 0) {
            float bv = fb1[c];
#pragma unroll
            for (int p = 0; p < 4; p++)
                sA[p][c] = fmaxf(acc[p] + sP[0][p][c] + sP[1][p][c] + sP[2][p][c] + bv, 0.f);
        }
        __syncthreads();
    }
    {
        float acc[4] = {0.f, 0.f, 0.f, 0.f};
        const float* W = fw2 + (q * 64) * 256 + c;
#pragma unroll 8
        for (int k = 0; k < 64; k++) {
            float wv = W[k * 256];
#pragma unroll
            for (int p = 0; p < 4; p++) acc[p] = fmaf(sA[p][q * 64 + k], wv, acc[p]);
        }
        if (q > 0) {
#pragma unroll
            for (int p = 0; p < 4; p++) sP[q - 1][p][c] = acc[p];
        }
        __syncthreads();
        if (q == 0) {
            float bv = fb2[c];
#pragma unroll
            for (int p = 0; p < 4; p++)
                sB[p][c] = fmaxf(acc[p] + sP[0][p][c] + sP[1][p][c] + sP[2][p][c] + bv, 0.f);
        }
        __syncthreads();
    }
    {
        float acc = 0.f;
        int p = 0, o = 0, qq = 0;
        bool act = (tid < 384);
        if (act) {
            p = tid / 96;
            int r = tid % 96;
            o = r % 24;
            qq = r / 24;
            const float* W = fw3 + (qq * 64) * 24 + o;
#pragma unroll 8
            for (int k = 0; k < 64; k++)
                acc = fmaf(sB[p][qq * 64 + k], W[k * 24], acc);
            if (qq > 0) sP[qq - 1][p][o] = acc;
        }
        __syncthreads();
        if (act && qq == 0)
            s_gen[p][o] = acc + sP[0][p][o] + sP[1][p][o] + sP[2][p][o] + fb3[o];
    }
    __syncthreads();

    // ---- Phase 2: SoftProjection ----
    {
        int wrp = tid >> 5;          // 0..31
        int lane = tid & 31;
        int p = wrp >> 3;
        int m = wrp & 7;
        int bp = pbase + p;
        float t = temperature[0];
        float sigma = fmaxf(t * t, 1e-4f);

        const float* PX = &g_patch[(bp * 3 + 0) * SS];
        const float* PY = &g_patch[(bp * 3 + 1) * SS];
        const float* PZ = &g_patch[(bp * 3 + 2) * SS];

        float qx = s_gen[p][m * 3 + 0];
        float qy = s_gen[p][m * 3 + 1];
        float qz = s_gen[p][m * 3 + 2];
        float q2 = qx * qx + qy * qy + qz * qz;

        float bd[7]; int bi[7];
#pragma unroll
        for (int k = 0; k < 7; k++) { bd[k] = 3.4e38f; bi[k] = 0; }

        for (int i = lane; i < SS; i += 32) {
            float px = PX[i], py = PY[i], pz = PZ[i];
            float p2 = px * px + py * py + pz * pz;
            float dot = qx * px + qy * py + qz * pz;
            float d = (q2 - 2.0f * dot) + p2;
            if (d < bd[6]) {
                bd[6] = d; bi[6] = i;
#pragma unroll
                for (int k = 6; k > 0; k--) {
                    if (bd[k] < bd[k - 1]) {
                        float td = bd[k]; bd[k] = bd[k - 1]; bd[k - 1] = td;
                        int ti = bi[k]; bi[k] = bi[k - 1]; bi[k - 1] = ti;
                    }
                }
            }
        }
        float selD[7]; int selI[7];
#pragma unroll
        for (int k = 0; k < 7; k++) {
            float mv = bd[0]; int ml = lane;
#pragma unroll
            for (int o = 16; o > 0; o >>= 1) {
                float ov = __shfl_xor_sync(0xffffffffu, mv, o);
                int ol = __shfl_xor_sync(0xffffffffu, ml, o);
                if (ov < mv || (ov == mv && ol < ml)) { mv = ov; ml = ol; }
            }
            selD[k] = mv;
            selI[k] = __shfl_sync(0xffffffffu, bi[0], ml);
            if (lane == ml) {
#pragma unroll
                for (int qd = 0; qd < 6; qd++) { bd[qd] = bd[qd + 1]; bi[qd] = bi[qd + 1]; }
                bd[6] = 3.4e38f;
            }
        }
        if (lane == 0) {
            float wsum = 0.f, sx = 0.f, sy = 0.f, sz = 0.f;
#pragma unroll
            for (int k = 0; k < 7; k++) {
                float wgt = expf((selD[0] - selD[k]) / sigma);
                int i = selI[k];
                wsum += wgt;
                sx = fmaf(wgt, PX[i], sx);
                sy = fmaf(wgt, PY[i], sy);
                sz = fmaf(wgt, PZ[i], sz);
            }
            float inv = 1.0f / wsum;
            float nrm = g_norm[bp];
            float mex = g_mean[bp * 3 + 0], mey = g_mean[bp * 3 + 1], mez = g_mean[bp * 3 + 2];
            int o = (bp * MM + m) * 3;
            out[o + 0] = fmaf(sx * inv, nrm, mex);
            out[o + 1] = fmaf(sy * inv, nrm, mey);
            out[o + 2] = fmaf(sz * inv, nrm, mez);
        }
    }
}

// =========================================================================
extern "C" void kernel_launch(void* const* d_in, const int* in_sizes, int n_in,
                              void* d_out, int out_size) {
    const float* xyz = (const float*)d_in[0];
    const float* mw0 = (const float*)d_in[1];  const float* mb0 = (const float*)d_in[2];
    const float* mw1 = (const float*)d_in[3];  const float* mb1 = (const float*)d_in[4];
    const float* mw2 = (const float*)d_in[5];  const float* mb2 = (const float*)d_in[6];
    const float* mw3 = (const float*)d_in[7];  const float* mb3 = (const float*)d_in[8];
    const float* mw4 = (const float*)d_in[9];  const float* mb4 = (const float*)d_in[10];
    const float* fw0 = (const float*)d_in[11]; const float* fb0 = (const float*)d_in[12];
    const float* fw1 = (const float*)d_in[13]; const float* fb1 = (const float*)d_in[14];
    const float* fw2 = (const float*)d_in[15]; const float* fb2 = (const float*)d_in[16];
    const float* fw3 = (const float*)d_in[17]; const float* fb3 = (const float*)d_in[18];
    const float* temp = (const float*)d_in[19];
    float* out = (float*)d_out;

    cudaFuncSetAttribute(mlp_mma_kernel, cudaFuncAttributeMaxDynamicSharedMemorySize,
                         DYN_TOT);

    fps_prep_kernel<<<BB, 1024>>>(xyz, mw0, mb0, mw1, mb1, mw2, mb2,
                                  mw3, mb3, mw4, mb4);
    knn_kernel<<<NPATCH, 512>>>(xyz);
    mlp_mma_kernel<<<NPATCH * 2, 256, DYN_TOT>>>();
    dec_proj_kernel<<<128, 1024>>>(fw0, fb0, fw1, fb1, fw2, fb2, fw3, fb3,
                                   temp, out);
}

// round 16
// speedup vs baseline: 1.0071x; 1.0071x over previous
#include <cuda_runtime.h>
#include <cuda_bf16.h>
#include <cstdint>

// ---------------- problem constants ----------------
#define BB 64
#define NN 8192
#define PP 8
#define SS 1024
#define MM 8
#define KK 7
#define NPATCH (BB*PP)   // 512

// ---------------- device scratch (no allocations allowed) ----------------
__device__ float g_seed[NPATCH * 3];
__device__ float g_patch[NPATCH * 3 * SS];      // normalized patch coords, SoA [bp][c][s]
__device__ float g_mean[NPATCH * 3];
__device__ float g_norm[NPATCH];
__device__ float g_feat[NPATCH * 128];          // maxpool accumulator (atomicMax on bits)

// smem/global weight-buffer layout (bytes)
#define O_W1H 0
#define O_W1L 3072
#define O_W2H 6144
#define O_W2L 15360
#define O_W3H 24576
#define O_W3L 33792
#define O_W4H 43008
#define O_W4L 61440
#define O_W5H 79872
#define O_W5L 114688
#define O_BIAS 149504        // 448 floats: b1@0 b2@64 b3@128 b4@192 b5@320
#define DYN_TOT 151296

__device__ __align__(16) unsigned char g_wbuf[DYN_TOT];

// =========================================================================
// helpers
// =========================================================================
__device__ __forceinline__ uint32_t smem_to_u32(const void* smem_ptr) {
    uint32_t addr;
    asm("{ .reg .u64 tmp; cvta.to.shared.u64 tmp, %1; cvt.u32.u64 %0, tmp; }"
        : "=r"(addr) : "l"(smem_ptr));
    return addr;
}

__device__ __forceinline__ void mma_bf16(float* c, const uint32_t* a, uint32_t b0, uint32_t b1) {
    asm volatile(
        "mma.sync.aligned.m16n8k16.row.col.f32.bf16.bf16.f32 "
        "{%0,%1,%2,%3}, {%4,%5,%6,%7}, {%8,%9}, {%0,%1,%2,%3};"
        : "+f"(c[0]), "+f"(c[1]), "+f"(c[2]), "+f"(c[3])
        : "r"(a[0]), "r"(a[1]), "r"(a[2]), "r"(a[3]), "r"(b0), "r"(b1));
}

__device__ __forceinline__ void ldm_x2(uint32_t& r0, uint32_t& r1, uint32_t addr) {
    asm volatile("ldmatrix.sync.aligned.m8n8.x2.shared.b16 {%0,%1}, [%2];"
                 : "=r"(r0), "=r"(r1) : "r"(addr));
}

// split (f0 -> low half, f1 -> high half) into hi/lo bf16x2 words.
__device__ __forceinline__ void split2(float f0, float f1, uint32_t& hi, uint32_t& lo) {
    uint32_t h, l;
    asm("cvt.rn.bf16x2.f32 %0, %1, %2;" : "=r"(h) : "f"(f1), "f"(f0));
    float r1 = __uint_as_float(h & 0xFFFF0000u);
    float r0 = __uint_as_float(h << 16);
    float d1 = f1 - r1;
    float d0 = f0 - r0;
    asm("cvt.rn.bf16x2.f32 %0, %1, %2;" : "=r"(l) : "f"(d1), "f"(d0));
    hi = h; lo = l;
}

// =========================================================================
// Kernel 0: pre-split weights (hi/lo bf16) into g_wbuf (smem-identical layout)
// =========================================================================
template<int K, int N, int STRIDE>
__device__ __forceinline__ void stage_wg(const float* __restrict__ w,
                                         char* hi, char* lo, int t, int nt) {
    for (int i = t; i < K * N; i += nt) {
        int k = i / N, n = i - k * N;
        float f = w[i];
        __nv_bfloat16 h = __float2bfloat16(f);
        __nv_bfloat16 l = __float2bfloat16(f - __bfloat162float(h));
        int off = n * STRIDE + k * 2;
        *(__nv_bfloat16*)(hi + off) = h;
        *(__nv_bfloat16*)(lo + off) = l;
    }
}

__global__ void prep_kernel(
    const float* __restrict__ mw0, const float* __restrict__ mb0,
    const float* __restrict__ mw1, const float* __restrict__ mb1,
    const float* __restrict__ mw2, const float* __restrict__ mb2,
    const float* __restrict__ mw3, const float* __restrict__ mb3,
    const float* __restrict__ mw4, const float* __restrict__ mb4) {
    int t = blockIdx.x * blockDim.x + threadIdx.x;
    int nt = gridDim.x * blockDim.x;
    char* B = (char*)g_wbuf;

    for (int i = t; i < 64 * 16; i += nt) {
        int n = i >> 4, k = i & 15;
        float f = (k < 3) ? mw0[k * 64 + n] : 0.f;
        __nv_bfloat16 h = __float2bfloat16(f);
        __nv_bfloat16 l = __float2bfloat16(f - __bfloat162float(h));
        int off = n * 48 + k * 2;
        *(__nv_bfloat16*)(B + O_W1H + off) = h;
        *(__nv_bfloat16*)(B + O_W1L + off) = l;
    }
    stage_wg<64, 64, 144>(mw1, B + O_W2H, B + O_W2L, t, nt);
    stage_wg<64, 64, 144>(mw2, B + O_W3H, B + O_W3L, t, nt);
    stage_wg<64, 128, 144>(mw3, B + O_W4H, B + O_W4L, t, nt);
    stage_wg<128, 128, 272>(mw4, B + O_W5H, B + O_W5L, t, nt);
    float* bias = (float*)(B + O_BIAS);
    for (int i = t; i < 64; i += nt) {
        bias[i] = mb0[i]; bias[64 + i] = mb1[i]; bias[128 + i] = mb2[i];
    }
    for (int i = t; i < 128; i += nt) {
        bias[192 + i] = mb3[i]; bias[320 + i] = mb4[i];
    }
}

// =========================================================================
// Kernel 1: farthest point sampling (register-cached coords, proven)
// =========================================================================
__global__ void fps_kernel(const float* __restrict__ xyz) {
    int b = blockIdx.x;
    const float* X = xyz + (size_t)b * 3 * NN;
    __shared__ float s_v[32];
    __shared__ int   s_i[32];
    __shared__ float s_c[3];
    __shared__ int   s_far;
    int tid = threadIdx.x;
    int lane = tid & 31;
    int wrp = tid >> 5;

    float cxr[8], cyr[8], czr[8], dist[8];
#pragma unroll
    for (int k = 0; k < 8; k++) {
        int i = tid + k * 1024;
        cxr[k] = X[i]; cyr[k] = X[NN + i]; czr[k] = X[2 * NN + i];
        dist[k] = 1e10f;
    }
    int far = 0;

    for (int it = 0; it < PP; it++) {
        if (tid == 0) {
            float fx = X[far], fy = X[NN + far], fz = X[2 * NN + far];
            s_c[0] = fx; s_c[1] = fy; s_c[2] = fz;
            g_seed[(b * PP + it) * 3 + 0] = fx;
            g_seed[(b * PP + it) * 3 + 1] = fy;
            g_seed[(b * PP + it) * 3 + 2] = fz;
        }
        __syncthreads();
        float cx = s_c[0], cy = s_c[1], cz = s_c[2];
        float bv = -1.0f; int bi = 0;
#pragma unroll
        for (int k = 0; k < 8; k++) {
            int i = tid + k * 1024;
            float dx = cxr[k] - cx, dy = cyr[k] - cy, dz = czr[k] - cz;
            float d = dx * dx + dy * dy + dz * dz;
            float nd = fminf(dist[k], d);
            dist[k] = nd;
            if (nd > bv || (nd == bv && i < bi)) { bv = nd; bi = i; }
        }
#pragma unroll
        for (int o = 16; o > 0; o >>= 1) {
            float ov = __shfl_xor_sync(0xffffffffu, bv, o);
            int oi = __shfl_xor_sync(0xffffffffu, bi, o);
            if (ov > bv || (ov == bv && oi < bi)) { bv = ov; bi = oi; }
        }
        if (lane == 0) { s_v[wrp] = bv; s_i[wrp] = bi; }
        __syncthreads();
        if (wrp == 0) {
            float mv = s_v[lane]; int mi = s_i[lane];
#pragma unroll
            for (int o = 16; o > 0; o >>= 1) {
                float ov = __shfl_xor_sync(0xffffffffu, mv, o);
                int oi = __shfl_xor_sync(0xffffffffu, mi, o);
                if (ov > mv || (ov == mv && oi < mi)) { mv = ov; mi = oi; }
            }
            if (lane == 0) s_far = mi;
        }
        __syncthreads();
        far = s_far;
        __syncthreads();
    }
}

// =========================================================================
// Kernel 2: KNN radix-select + patch normalization (proven, round 7)
// =========================================================================
__global__ void __launch_bounds__(512) knn_kernel(const float* __restrict__ xyz) {
    int bp = blockIdx.x;
    int b = bp >> 3;
    const float* X = xyz + (size_t)b * 3 * NN;
    __shared__ unsigned s_key[NN];
    __shared__ int s_sel[SS];
    __shared__ int s_hist[512];
    __shared__ unsigned s_pref;
    __shared__ int s_kk;
    __shared__ int s_cnt[2];
    __shared__ float s_red[512];
    int tid = threadIdx.x;
    int lane = tid & 31;

    if (tid < 128) g_feat[bp * 128 + tid] = 0.f;

    float sx = g_seed[bp * 3 + 0], sy = g_seed[bp * 3 + 1], sz = g_seed[bp * 3 + 2];
    float s2 = sx * sx + sy * sy + sz * sz;

    for (int i = tid; i < NN; i += 512) {
        float px = X[i], py = X[NN + i], pz = X[2 * NN + i];
        float p2 = px * px + py * py + pz * pz;
        float dot = sx * px + sy * py + sz * pz;
        float d = (s2 - 2.0f * dot) + p2;
        unsigned u = __float_as_uint(d);
        u = (u & 0x80000000u) ? ~u : (u | 0x80000000u);
        s_key[i] = u;
    }
    if (tid == 0) { s_pref = 0u; s_kk = SS; }
    __syncthreads();

    unsigned prefix = 0, maskHi = 0;
    int bank = ((tid >> 5) & 1) * 256;
    for (int pass = 0; pass < 4; pass++) {
        int shift = 24 - 8 * pass;
        s_hist[tid] = 0;
        __syncthreads();
        for (int i = tid; i < NN; i += 512) {
            unsigned u = s_key[i];
            if ((u & maskHi) == prefix) atomicAdd(&s_hist[bank + ((u >> shift) & 255)], 1);
        }
        __syncthreads();
        if (tid < 32) {
            int kk = s_kk;
            unsigned pref = s_pref;
            int sv[8]; int tot = 0;
#pragma unroll
            for (int j = 0; j < 8; j++) {
                int v = s_hist[lane * 8 + j] + s_hist[256 + lane * 8 + j];
                sv[j] = v; tot += v;
            }
            int run = tot;
#pragma unroll
            for (int o = 1; o < 32; o <<= 1) {
                int v = __shfl_up_sync(0xffffffffu, run, o);
                if (lane >= o) run += v;
            }
            int excl = run - tot;
            if (kk > excl && kk <= run) {
                int cum = excl;
#pragma unroll
                for (int j = 0; j < 8; j++) {
                    if (cum + sv[j] >= kk) {
                        s_pref = pref | ((unsigned)(lane * 8 + j) << shift);
                        s_kk = kk - cum;
                        break;
                    }
                    cum += sv[j];
                }
            }
        }
        __syncthreads();
        prefix = s_pref;
        maskHi |= (0xFFu << shift);
        __syncthreads();
    }
    unsigned T = prefix;

    if (tid == 0) { s_cnt[0] = 0; s_cnt[1] = 0; }
    __syncthreads();
    for (int i = tid; i < NN; i += 512) {
        bool pred = s_key[i] < T;
        unsigned m = __ballot_sync(0xffffffffu, pred);
        int cnt = __popc(m);
        int base = 0;
        if (lane == 0 && cnt) base = atomicAdd(&s_cnt[0], cnt);
        base = __shfl_sync(0xffffffffu, base, 0);
        if (pred) s_sel[base + __popc(m & ((1u << lane) - 1u))] = i;
    }
    __syncthreads();
    int nLess = s_cnt[0];
    for (int i = tid; i < NN; i += 512) {
        bool pred = s_key[i] == T;
        unsigned m = __ballot_sync(0xffffffffu, pred);
        int cnt = __popc(m);
        int base = 0;
        if (lane == 0 && cnt) base = atomicAdd(&s_cnt[1], cnt);
        base = __shfl_sync(0xffffffffu, base, 0);
        if (pred) {
            int pos = nLess + base + __popc(m & ((1u << lane) - 1u));
            if (pos < SS) s_sel[pos] = i;
        }
    }
    __syncthreads();

    float* cxs = (float*)s_key;
    float* cys = cxs + SS;
    float* czs = cxs + 2 * SS;
    float ax = 0.f, ay = 0.f, az = 0.f;
    for (int j = tid; j < SS; j += 512) {
        int i = s_sel[j];
        float px = X[i], py = X[NN + i], pz = X[2 * NN + i];
        cxs[j] = px; cys[j] = py; czs[j] = pz;
        ax += px; ay += py; az += pz;
    }
    s_red[tid] = ax; __syncthreads();
    for (int s = 256; s > 0; s >>= 1) { if (tid < s) s_red[tid] += s_red[tid + s]; __syncthreads(); }
    float mx = s_red[0] * (1.0f / SS); __syncthreads();
    s_red[tid] = ay; __syncthreads();
    for (int s = 256; s > 0; s >>= 1) { if (tid < s) s_red[tid] += s_red[tid + s]; __syncthreads(); }
    float my = s_red[0] * (1.0f / SS); __syncthreads();
    s_red[tid] = az; __syncthreads();
    for (int s = 256; s > 0; s >>= 1) { if (tid < s) s_red[tid] += s_red[tid + s]; __syncthreads(); }
    float mz = s_red[0] * (1.0f / SS); __syncthreads();

    float mnorm = 0.f;
    for (int j = tid; j < SS; j += 512) {
        float dx = cxs[j] - mx, dy = cys[j] - my, dz = czs[j] - mz;
        float l = sqrtf(dx * dx + dy * dy + dz * dz);
        mnorm = fmaxf(mnorm, l);
    }
    s_red[tid] = mnorm; __syncthreads();
    for (int s = 256; s > 0; s >>= 1) { if (tid < s) s_red[tid] = fmaxf(s_red[tid], s_red[tid + s]); __syncthreads(); }
    float nrm = s_red[0]; __syncthreads();

    for (int j = tid; j < SS; j += 512) {
        g_patch[(bp * 3 + 0) * SS + j] = (cxs[j] - mx) / nrm;
        g_patch[(bp * 3 + 1) * SS + j] = (cys[j] - my) / nrm;
        g_patch[(bp * 3 + 2) * SS + j] = (czs[j] - mz) / nrm;
    }
    if (tid == 0) {
        g_mean[bp * 3 + 0] = mx; g_mean[bp * 3 + 1] = my; g_mean[bp * 3 + 2] = mz;
        g_norm[bp] = nrm;
    }
}

// =========================================================================
// Kernel 3: fused MLP — EXACT Round-9 configuration (best measured: 263.3us).
// =========================================================================
template<int KC, int NT, int STRIDE>
__device__ __forceinline__ void layer_forward2(
    const uint32_t (*Ah0)[4], const uint32_t (*Al0)[4],
    const uint32_t (*Ah1)[4], const uint32_t (*Al1)[4],
    uint32_t wH, uint32_t wL, const float* __restrict__ bias, int lane,
    uint32_t (*Oh0)[4], uint32_t (*Ol0)[4],
    uint32_t (*Oh1)[4], uint32_t (*Ol1)[4]) {
    uint32_t lm = (uint32_t)(lane & 7) * STRIDE + (uint32_t)((lane >> 3) & 1) * 16;
    int t4 = lane & 3;
#pragma unroll
    for (int np = 0; np < NT / 2; np++) {
        float ccA[2][4], ccB[2][4];
#pragma unroll
        for (int sub = 0; sub < 2; sub++) {
            int nt = np * 2 + sub;
            uint32_t ro = lm + (uint32_t)nt * 8u * STRIDE;
            float c1a[4] = {0.f, 0.f, 0.f, 0.f}, c2a[4] = {0.f, 0.f, 0.f, 0.f};
            float c1b[4] = {0.f, 0.f, 0.f, 0.f}, c2b[4] = {0.f, 0.f, 0.f, 0.f};
#pragma unroll
            for (int kc = 0; kc < KC; kc++) {
                uint32_t b0, b1, l0, l1;
                ldm_x2(b0, b1, wH + ro + kc * 32);
                ldm_x2(l0, l1, wL + ro + kc * 32);
                mma_bf16(c1a, Ah0[kc], b0, b1);
                mma_bf16(c1b, Ah1[kc], b0, b1);
                mma_bf16(c2a, Ah0[kc], l0, l1);
                mma_bf16(c2b, Ah1[kc], l0, l1);
                mma_bf16(c2a, Al0[kc], b0, b1);
                mma_bf16(c2b, Al1[kc], b0, b1);
            }
            float2 bb = *reinterpret_cast<const float2*>(bias + nt * 8 + t4 * 2);
            ccA[sub][0] = fmaxf(c1a[0] + c2a[0] + bb.x, 0.f);
            ccA[sub][1] = fmaxf(c1a[1] + c2a[1] + bb.y, 0.f);
            ccA[sub][2] = fmaxf(c1a[2] + c2a[2] + bb.x, 0.f);
            ccA[sub][3] = fmaxf(c1a[3] + c2a[3] + bb.y, 0.f);
            ccB[sub][0] = fmaxf(c1b[0] + c2b[0] + bb.x, 0.f);
            ccB[sub][1] = fmaxf(c1b[1] + c2b[1] + bb.y, 0.f);
            ccB[sub][2] = fmaxf(c1b[2] + c2b[2] + bb.x, 0.f);
            ccB[sub][3] = fmaxf(c1b[3] + c2b[3] + bb.y, 0.f);
        }
        split2(ccA[0][0], ccA[0][1], Oh0[np][0], Ol0[np][0]);
        split2(ccA[0][2], ccA[0][3], Oh0[np][1], Ol0[np][1]);
        split2(ccA[1][0], ccA[1][1], Oh0[np][2], Ol0[np][2]);
        split2(ccA[1][2], ccA[1][3], Oh0[np][3], Ol0[np][3]);
        split2(ccB[0][0], ccB[0][1], Oh1[np][0], Ol1[np][0]);
        split2(ccB[0][2], ccB[0][3], Oh1[np][1], Ol1[np][1]);
        split2(ccB[1][0], ccB[1][1], Oh1[np][2], Ol1[np][2]);
        split2(ccB[1][2], ccB[1][3], Oh1[np][3], Ol1[np][3]);
    }
}

template<int KC, int NT, int STRIDE>
__device__ __forceinline__ void layer_final2(
    const uint32_t (*Ah0)[4], const uint32_t (*Al0)[4],
    const uint32_t (*Ah1)[4], const uint32_t (*Al1)[4],
    uint32_t wH, uint32_t wL, const float* __restrict__ bias, int lane, int* smax) {
    uint32_t lm = (uint32_t)(lane & 7) * STRIDE + (uint32_t)((lane >> 3) & 1) * 16;
    int t4 = lane & 3;
#pragma unroll
    for (int nt = 0; nt < NT; nt++) {
        uint32_t ro = lm + (uint32_t)nt * 8u * STRIDE;
        float c1a[4] = {0.f, 0.f, 0.f, 0.f}, c2a[4] = {0.f, 0.f, 0.f, 0.f};
        float c1b[4] = {0.f, 0.f, 0.f, 0.f}, c2b[4] = {0.f, 0.f, 0.f, 0.f};
#pragma unroll
        for (int kc = 0; kc < KC; kc++) {
            uint32_t b0, b1, l0, l1;
            ldm_x2(b0, b1, wH + ro + kc * 32);
            ldm_x2(l0, l1, wL + ro + kc * 32);
            mma_bf16(c1a, Ah0[kc], b0, b1);
            mma_bf16(c1b, Ah1[kc], b0, b1);
            mma_bf16(c2a, Ah0[kc], l0, l1);
            mma_bf16(c2b, Ah1[kc], l0, l1);
            mma_bf16(c2a, Al0[kc], b0, b1);
            mma_bf16(c2b, Al1[kc], b0, b1);
        }
        float2 bb = *reinterpret_cast<const float2*>(bias + nt * 8 + t4 * 2);
        float v0a = fmaxf(c1a[0] + c2a[0] + bb.x, 0.f), v2a = fmaxf(c1a[2] + c2a[2] + bb.x, 0.f);
        float v1a = fmaxf(c1a[1] + c2a[1] + bb.y, 0.f), v3a = fmaxf(c1a[3] + c2a[3] + bb.y, 0.f);
        float v0b = fmaxf(c1b[0] + c2b[0] + bb.x, 0.f), v2b = fmaxf(c1b[2] + c2b[2] + bb.x, 0.f);
        float v1b = fmaxf(c1b[1] + c2b[1] + bb.y, 0.f), v3b = fmaxf(c1b[3] + c2b[3] + bb.y, 0.f);
        float m0 = fmaxf(fmaxf(v0a, v2a), fmaxf(v0b, v2b));
        float m1 = fmaxf(fmaxf(v1a, v3a), fmaxf(v1b, v3b));
#pragma unroll
        for (int off = 4; off < 32; off <<= 1) {
            m0 = fmaxf(m0, __shfl_xor_sync(0xffffffffu, m0, off));
            m1 = fmaxf(m1, __shfl_xor_sync(0xffffffffu, m1, off));
        }
        if (lane < 4) {
            atomicMax(&smax[nt * 8 + 2 * lane], __float_as_int(m0));
            atomicMax(&smax[nt * 8 + 2 * lane + 1], __float_as_int(m1));
        }
    }
}

__global__ void __launch_bounds__(256, 1) mlp_mma_kernel() {
    extern __shared__ char sm[];
    __shared__ int smax[128];
    int bp2 = blockIdx.x;
    int bp = bp2 >> 1;
    int half = bp2 & 1;
    int tid = threadIdx.x;
    int lane = tid & 31;
    int w = tid >> 5;
    uint32_t sbase = smem_to_u32(sm);

    if (tid < 128) smax[tid] = 0;
    {
        const uint4* src = (const uint4*)g_wbuf;
        uint4* dst = (uint4*)sm;
        for (int i = tid; i < DYN_TOT / 16; i += 256) dst[i] = src[i];
    }
    __syncthreads();

    const float* sbias = (const float*)(sm + O_BIAS);
    const float* PX = &g_patch[(bp * 3 + 0) * SS];
    const float* PY = &g_patch[(bp * 3 + 1) * SS];
    const float* PZ = &g_patch[(bp * 3 + 2) * SS];
    int t4 = lane & 3;

    for (int it = 0; it < 2; it++) {
        int pbase = half * 512 + it * 256 + w * 32 + (lane >> 2);
        float x0 = PX[pbase], y0 = PY[pbase], z0 = PZ[pbase];
        float x1 = PX[pbase + 8], y1 = PY[pbase + 8], z1 = PZ[pbase + 8];
        float x2 = PX[pbase + 16], y2 = PY[pbase + 16], z2 = PZ[pbase + 16];
        float x3 = PX[pbase + 24], y3 = PY[pbase + 24], z3 = PZ[pbase + 24];

        uint32_t A1h0[1][4] = {{0u, 0u, 0u, 0u}}, A1l0[1][4] = {{0u, 0u, 0u, 0u}};
        uint32_t A1h1[1][4] = {{0u, 0u, 0u, 0u}}, A1l1[1][4] = {{0u, 0u, 0u, 0u}};
        if (t4 == 0) {
            split2(x0, y0, A1h0[0][0], A1l0[0][0]);
            split2(x1, y1, A1h0[0][1], A1l0[0][1]);
            split2(x2, y2, A1h1[0][0], A1l1[0][0]);
            split2(x3, y3, A1h1[0][1], A1l1[0][1]);
        } else if (t4 == 1) {
            split2(z0, 0.f, A1h0[0][0], A1l0[0][0]);
            split2(z1, 0.f, A1h0[0][1], A1l0[0][1]);
            split2(z2, 0.f, A1h1[0][0], A1l1[0][0]);
            split2(z3, 0.f, A1h1[0][1], A1l1[0][1]);
        }

        uint32_t A2h0[4][4], A2l0[4][4], A2h1[4][4], A2l1[4][4];
        uint32_t A3h0[4][4], A3l0[4][4], A3h1[4][4], A3l1[4][4];
        uint32_t A4h0[4][4], A4l0[4][4], A4h1[4][4], A4l1[4][4];
        uint32_t A5h0[8][4], A5l0[8][4], A5h1[8][4], A5l1[8][4];

        layer_forward2<1, 8, 48>(A1h0, A1l0, A1h1, A1l1,
            sbase + O_W1H, sbase + O_W1L, sbias + 0, lane,
            A2h0, A2l0, A2h1, A2l1);
        layer_forward2<4, 8, 144>(A2h0, A2l0, A2h1, A2l1,
            sbase + O_W2H, sbase + O_W2L, sbias + 64, lane,
            A3h0, A3l0, A3h1, A3l1);
        layer_forward2<4, 8, 144>(A3h0, A3l0, A3h1, A3l1,
            sbase + O_W3H, sbase + O_W3L, sbias + 128, lane,
            A4h0, A4l0, A4h1, A4l1);
        layer_forward2<4, 16, 144>(A4h0, A4l0, A4h1, A4l1,
            sbase + O_W4H, sbase + O_W4L, sbias + 192, lane,
            A5h0, A5l0, A5h1, A5l1);
        layer_final2<8, 16, 272>(A5h0, A5l0, A5h1, A5l1,
            sbase + O_W5H, sbase + O_W5L, sbias + 320, lane, smax);
    }
    __syncthreads();
    if (tid < 128) atomicMax((int*)&g_feat[bp * 128 + tid], smax[tid]);
}

// =========================================================================
// Kernel 4: FUSED FC decoder + SoftProjection (proven, round 14).
// =========================================================================
__global__ void __launch_bounds__(1024) dec_proj_kernel(
    const float* __restrict__ fw0, const float* __restrict__ fb0,
    const float* __restrict__ fw1, const float* __restrict__ fb1,
    const float* __restrict__ fw2, const float* __restrict__ fb2,
    const float* __restrict__ fw3, const float* __restrict__ fb3,
    const float* __restrict__ temperature,
    float* __restrict__ out) {
    int pbase = blockIdx.x * 4;
    int tid = threadIdx.x;
    int c = tid & 255;
    int q = tid >> 8;            // k-quarter 0..3
    __shared__ float sA[4][256];
    __shared__ float sB[4][256];
    __shared__ float sP[3][4][256];
    __shared__ float s_gen[4][24];

    if (tid < 512) {
        int p = tid >> 7, cc = tid & 127;
        sA[p][cc] = g_feat[(pbase + p) * 128 + cc];
    }
    __syncthreads();

    {
        float acc[4] = {0.f, 0.f, 0.f, 0.f};
        const float* W = fw0 + (q * 32) * 256 + c;
#pragma unroll 8
        for (int k = 0; k < 32; k++) {
            float wv = W[k * 256];
#pragma unroll
            for (int p = 0; p < 4; p++) acc[p] = fmaf(sA[p][q * 32 + k], wv, acc[p]);
        }
        if (q > 0) {
#pragma unroll
            for (int p = 0; p < 4; p++) sP[q - 1][p][c] = acc[p];
        }
        __syncthreads();
        if (q == 0) {
            float bv = fb0[c];
#pragma unroll
            for (int p = 0; p < 4; p++)
                sB[p][c] = fmaxf(acc[p] + sP[0][p][c] + sP[1][p][c] + sP[2][p][c] + bv, 0.f);
        }
        __syncthreads();
    }
    {
        float acc[4] = {0.f, 0.f, 0.f, 0.f};
        const float* W = fw1 + (q * 64) * 256 + c;
#pragma unroll 8
        for (int k = 0; k < 64; k++) {
            float wv = W[k * 256];
#pragma unroll
            for (int p = 0; p < 4; p++) acc[p] = fmaf(sB[p][q * 64 + k], wv, acc[p]);
        }
        if (q > 0) {
#pragma unroll
            for (int p = 0; p < 4; p++) sP[q - 1][p][c] = acc[p];
        }
        __syncthreads();
        if (q == 0) {
            float bv = fb1[c];
#pragma unroll
            for (int p = 0; p < 4; p++)
                sA[p][c] = fmaxf(acc[p] + sP[0][p][c] + sP[1][p][c] + sP[2][p][c] + bv, 0.f);
        }
        __syncthreads();
    }
    {
        float acc[4] = {0.f, 0.f, 0.f, 0.f};
        const float* W = fw2 + (q * 64) * 256 + c;
#pragma unroll 8
        for (int k = 0; k < 64; k++) {
            float wv = W[k * 256];
#pragma unroll
            for (int p = 0; p < 4; p++) acc[p] = fmaf(sA[p][q * 64 + k], wv, acc[p]);
        }
        if (q > 0) {
#pragma unroll
            for (int p = 0; p < 4; p++) sP[q - 1][p][c] = acc[p];
        }
        __syncthreads();
        if (q == 0) {
            float bv = fb2[c];
#pragma unroll
            for (int p = 0; p < 4; p++)
                sB[p][c] = fmaxf(acc[p] + sP[0][p][c] + sP[1][p][c] + sP[2][p][c] + bv, 0.f);
        }
        __syncthreads();
    }
    {
        float acc = 0.f;
        int p = 0, o = 0, qq = 0;
        bool act = (tid < 384);
        if (act) {
            p = tid / 96;
            int r = tid % 96;
            o = r % 24;
            qq = r / 24;
            const float* W = fw3 + (qq * 64) * 24 + o;
#pragma unroll 8
            for (int k = 0; k < 64; k++)
                acc = fmaf(sB[p][qq * 64 + k], W[k * 24], acc);
            if (qq > 0) sP[qq - 1][p][o] = acc;
        }
        __syncthreads();
        if (act && qq == 0)
            s_gen[p][o] = acc + sP[0][p][o] + sP[1][p][o] + sP[2][p][o] + fb3[o];
    }
    __syncthreads();

    // ---- Phase 2: SoftProjection ----
    {
        int wrp = tid >> 5;          // 0..31
        int lane = tid & 31;
        int p = wrp >> 3;
        int m = wrp & 7;
        int bp = pbase + p;
        float t = temperature[0];
        float sigma = fmaxf(t * t, 1e-4f);

        const float* PX = &g_patch[(bp * 3 + 0) * SS];
        const float* PY = &g_patch[(bp * 3 + 1) * SS];
        const float* PZ = &g_patch[(bp * 3 + 2) * SS];

        float qx = s_gen[p][m * 3 + 0];
        float qy = s_gen[p][m * 3 + 1];
        float qz = s_gen[p][m * 3 + 2];
        float q2 = qx * qx + qy * qy + qz * qz;

        float bd[7]; int bi[7];
#pragma unroll
        for (int k = 0; k < 7; k++) { bd[k] = 3.4e38f; bi[k] = 0; }

        for (int i = lane; i < SS; i += 32) {
            float px = PX[i], py = PY[i], pz = PZ[i];
            float p2 = px * px + py * py + pz * pz;
            float dot = qx * px + qy * py + qz * pz;
            float d = (q2 - 2.0f * dot) + p2;
            if (d < bd[6]) {
                bd[6] = d; bi[6] = i;
#pragma unroll
                for (int k = 6; k > 0; k--) {
                    if (bd[k] < bd[k - 1]) {
                        float td = bd[k]; bd[k] = bd[k - 1]; bd[k - 1] = td;
                        int ti = bi[k]; bi[k] = bi[k - 1]; bi[k - 1] = ti;
                    }
                }
            }
        }
        float selD[7]; int selI[7];
#pragma unroll
        for (int k = 0; k < 7; k++) {
            float mv = bd[0]; int ml = lane;
#pragma unroll
            for (int o = 16; o > 0; o >>= 1) {
                float ov = __shfl_xor_sync(0xffffffffu, mv, o);
                int ol = __shfl_xor_sync(0xffffffffu, ml, o);
                if (ov < mv || (ov == mv && ol < ml)) { mv = ov; ml = ol; }
            }
            selD[k] = mv;
            selI[k] = __shfl_sync(0xffffffffu, bi[0], ml);
            if (lane == ml) {
#pragma unroll
                for (int qd = 0; qd < 6; qd++) { bd[qd] = bd[qd + 1]; bi[qd] = bi[qd + 1]; }
                bd[6] = 3.4e38f;
            }
        }
        if (lane == 0) {
            float wsum = 0.f, sx = 0.f, sy = 0.f, sz = 0.f;
#pragma unroll
            for (int k = 0; k < 7; k++) {
                float wgt = expf((selD[0] - selD[k]) / sigma);
                int i = selI[k];
                wsum += wgt;
                sx = fmaf(wgt, PX[i], sx);
                sy = fmaf(wgt, PY[i], sy);
                sz = fmaf(wgt, PZ[i], sz);
            }
            float inv = 1.0f / wsum;
            float nrm = g_norm[bp];
            float mex = g_mean[bp * 3 + 0], mey = g_mean[bp * 3 + 1], mez = g_mean[bp * 3 + 2];
            int o = (bp * MM + m) * 3;
            out[o + 0] = fmaf(sx * inv, nrm, mex);
            out[o + 1] = fmaf(sy * inv, nrm, mey);
            out[o + 2] = fmaf(sz * inv, nrm, mez);
        }
    }
}

// =========================================================================
extern "C" void kernel_launch(void* const* d_in, const int* in_sizes, int n_in,
                              void* d_out, int out_size) {
    const float* xyz = (const float*)d_in[0];
    const float* mw0 = (const float*)d_in[1];  const float* mb0 = (const float*)d_in[2];
    const float* mw1 = (const float*)d_in[3];  const float* mb1 = (const float*)d_in[4];
    const float* mw2 = (const float*)d_in[5];  const float* mb2 = (const float*)d_in[6];
    const float* mw3 = (const float*)d_in[7];  const float* mb3 = (const float*)d_in[8];
    const float* mw4 = (const float*)d_in[9];  const float* mb4 = (const float*)d_in[10];
    const float* fw0 = (const float*)d_in[11]; const float* fb0 = (const float*)d_in[12];
    const float* fw1 = (const float*)d_in[13]; const float* fb1 = (const float*)d_in[14];
    const float* fw2 = (const float*)d_in[15]; const float* fb2 = (const float*)d_in[16];
    const float* fw3 = (const float*)d_in[17]; const float* fb3 = (const float*)d_in[18];
    const float* temp = (const float*)d_in[19];
    float* out = (float*)d_out;

    cudaFuncSetAttribute(mlp_mma_kernel, cudaFuncAttributeMaxDynamicSharedMemorySize,
                         DYN_TOT);

    prep_kernel<<<48, 256>>>(mw0, mb0, mw1, mb1, mw2, mb2, mw3, mb3, mw4, mb4);
    fps_kernel<<<BB, 1024>>>(xyz);
    knn_kernel<<<NPATCH, 512>>>(xyz);
    mlp_mma_kernel<<<NPATCH * 2, 256, DYN_TOT>>>();
    dec_proj_kernel<<<128, 1024>>>(fw0, fb0, fw1, fb1, fw2, fb2, fw3, fb3,
                                   temp, out);
}

// round 17
// speedup vs baseline: 1.0073x; 1.0002x over previous
#include <cuda_runtime.h>
#include <cuda_bf16.h>
#include <cstdint>

// ---------------- problem constants ----------------
#define BB 64
#define NN 8192
#define PP 8
#define SS 1024
#define MM 8
#define KK 7
#define NPATCH (BB*PP)   // 512

// ---------------- device scratch (no allocations allowed) ----------------
__device__ float g_seed[NPATCH * 3];
__device__ float g_patch[NPATCH * 3 * SS];      // normalized patch coords, SoA [bp][c][s]
__device__ float g_mean[NPATCH * 3];
__device__ float g_norm[NPATCH];
__device__ float g_feat[NPATCH * 128];          // maxpool accumulator (atomicMax on bits)

// smem/global weight-buffer layout (bytes)
#define O_W1H 0
#define O_W1L 3072
#define O_W2H 6144
#define O_W2L 15360
#define O_W3H 24576
#define O_W3L 33792
#define O_W4H 43008
#define O_W4L 61440
#define O_W5H 79872
#define O_W5L 114688
#define O_BIAS 149504        // 448 floats: b1@0 b2@64 b3@128 b4@192 b5@320
#define DYN_TOT 151296

__device__ __align__(16) unsigned char g_wbuf[DYN_TOT];

// =========================================================================
// helpers
// =========================================================================
__device__ __forceinline__ uint32_t smem_to_u32(const void* smem_ptr) {
    uint32_t addr;
    asm("{ .reg .u64 tmp; cvta.to.shared.u64 tmp, %1; cvt.u32.u64 %0, tmp; }"
        : "=r"(addr) : "l"(smem_ptr));
    return addr;
}

__device__ __forceinline__ void mma_bf16(float* c, const uint32_t* a, uint32_t b0, uint32_t b1) {
    asm volatile(
        "mma.sync.aligned.m16n8k16.row.col.f32.bf16.bf16.f32 "
        "{%0,%1,%2,%3}, {%4,%5,%6,%7}, {%8,%9}, {%0,%1,%2,%3};"
        : "+f"(c[0]), "+f"(c[1]), "+f"(c[2]), "+f"(c[3])
        : "r"(a[0]), "r"(a[1]), "r"(a[2]), "r"(a[3]), "r"(b0), "r"(b1));
}

__device__ __forceinline__ void ldm_x2(uint32_t& r0, uint32_t& r1, uint32_t addr) {
    asm volatile("ldmatrix.sync.aligned.m8n8.x2.shared.b16 {%0,%1}, [%2];"
                 : "=r"(r0), "=r"(r1) : "r"(addr));
}

// split (f0 -> low half, f1 -> high half) into hi/lo bf16x2 words.
__device__ __forceinline__ void split2(float f0, float f1, uint32_t& hi, uint32_t& lo) {
    uint32_t h, l;
    asm("cvt.rn.bf16x2.f32 %0, %1, %2;" : "=r"(h) : "f"(f1), "f"(f0));
    float r1 = __uint_as_float(h & 0xFFFF0000u);
    float r0 = __uint_as_float(h << 16);
    float d1 = f1 - r1;
    float d0 = f0 - r0;
    asm("cvt.rn.bf16x2.f32 %0, %1, %2;" : "=r"(l) : "f"(d1), "f"(d0));
    hi = h; lo = l;
}

// =========================================================================
// weight staging helper (shared by the knn-embedded prep)
// =========================================================================
template<int K, int N, int STRIDE>
__device__ __forceinline__ void stage_wg(const float* __restrict__ w,
                                         char* hi, char* lo, int t, int nt) {
    for (int i = t; i < K * N; i += nt) {
        int k = i / N, n = i - k * N;
        float f = w[i];
        __nv_bfloat16 h = __float2bfloat16(f);
        __nv_bfloat16 l = __float2bfloat16(f - __bfloat162float(h));
        int off = n * STRIDE + k * 2;
        *(__nv_bfloat16*)(hi + off) = h;
        *(__nv_bfloat16*)(lo + off) = l;
    }
}

// =========================================================================
// Kernel 1: farthest point sampling (register-cached coords, proven)
// =========================================================================
__global__ void fps_kernel(const float* __restrict__ xyz) {
    int b = blockIdx.x;
    const float* X = xyz + (size_t)b * 3 * NN;
    __shared__ float s_v[32];
    __shared__ int   s_i[32];
    __shared__ float s_c[3];
    __shared__ int   s_far;
    int tid = threadIdx.x;
    int lane = tid & 31;
    int wrp = tid >> 5;

    float cxr[8], cyr[8], czr[8], dist[8];
#pragma unroll
    for (int k = 0; k < 8; k++) {
        int i = tid + k * 1024;
        cxr[k] = X[i]; cyr[k] = X[NN + i]; czr[k] = X[2 * NN + i];
        dist[k] = 1e10f;
    }
    int far = 0;

    for (int it = 0; it < PP; it++) {
        if (tid == 0) {
            float fx = X[far], fy = X[NN + far], fz = X[2 * NN + far];
            s_c[0] = fx; s_c[1] = fy; s_c[2] = fz;
            g_seed[(b * PP + it) * 3 + 0] = fx;
            g_seed[(b * PP + it) * 3 + 1] = fy;
            g_seed[(b * PP + it) * 3 + 2] = fz;
        }
        __syncthreads();
        float cx = s_c[0], cy = s_c[1], cz = s_c[2];
        float bv = -1.0f; int bi = 0;
#pragma unroll
        for (int k = 0; k < 8; k++) {
            int i = tid + k * 1024;
            float dx = cxr[k] - cx, dy = cyr[k] - cy, dz = czr[k] - cz;
            float d = dx * dx + dy * dy + dz * dz;
            float nd = fminf(dist[k], d);
            dist[k] = nd;
            if (nd > bv || (nd == bv && i < bi)) { bv = nd; bi = i; }
        }
#pragma unroll
        for (int o = 16; o > 0; o >>= 1) {
            float ov = __shfl_xor_sync(0xffffffffu, bv, o);
            int oi = __shfl_xor_sync(0xffffffffu, bi, o);
            if (ov > bv || (ov == bv && oi < bi)) { bv = ov; bi = oi; }
        }
        if (lane == 0) { s_v[wrp] = bv; s_i[wrp] = bi; }
        __syncthreads();
        if (wrp == 0) {
            float mv = s_v[lane]; int mi = s_i[lane];
#pragma unroll
            for (int o = 16; o > 0; o >>= 1) {
                float ov = __shfl_xor_sync(0xffffffffu, mv, o);
                int oi = __shfl_xor_sync(0xffffffffu, mi, o);
                if (ov > mv || (ov == mv && oi < mi)) { mv = ov; mi = oi; }
            }
            if (lane == 0) s_far = mi;
        }
        __syncthreads();
        far = s_far;
        __syncthreads();
    }
}

// =========================================================================
// Kernel 2: KNN radix-select + patch normalization (proven, round 7)
// + embedded 1/512 share of weight pre-splitting (replaces prep_kernel).
// =========================================================================
__global__ void __launch_bounds__(512) knn_kernel(
    const float* __restrict__ xyz,
    const float* __restrict__ mw0, const float* __restrict__ mb0,
    const float* __restrict__ mw1, const float* __restrict__ mb1,
    const float* __restrict__ mw2, const float* __restrict__ mb2,
    const float* __restrict__ mw3, const float* __restrict__ mb3,
    const float* __restrict__ mw4, const float* __restrict__ mb4) {
    int bp = blockIdx.x;
    int b = bp >> 3;
    const float* X = xyz + (size_t)b * 3 * NN;
    __shared__ unsigned s_key[NN];
    __shared__ int s_sel[SS];
    __shared__ int s_hist[512];
    __shared__ unsigned s_pref;
    __shared__ int s_kk;
    __shared__ int s_cnt[2];
    __shared__ float s_red[512];
    int tid = threadIdx.x;
    int lane = tid & 31;

    // ---- embedded weight prep: this block's 1/512 share (~150 elements) ----
    {
        int t = bp * 512 + tid;
        int nt = NPATCH * 512;
        char* B = (char*)g_wbuf;
        for (int i = t; i < 64 * 16; i += nt) {
            int n = i >> 4, k = i & 15;
            float f = (k < 3) ? mw0[k * 64 + n] : 0.f;
            __nv_bfloat16 h = __float2bfloat16(f);
            __nv_bfloat16 l = __float2bfloat16(f - __bfloat162float(h));
            int off = n * 48 + k * 2;
            *(__nv_bfloat16*)(B + O_W1H + off) = h;
            *(__nv_bfloat16*)(B + O_W1L + off) = l;
        }
        stage_wg<64, 64, 144>(mw1, B + O_W2H, B + O_W2L, t, nt);
        stage_wg<64, 64, 144>(mw2, B + O_W3H, B + O_W3L, t, nt);
        stage_wg<64, 128, 144>(mw3, B + O_W4H, B + O_W4L, t, nt);
        stage_wg<128, 128, 272>(mw4, B + O_W5H, B + O_W5L, t, nt);
        float* bias = (float*)(B + O_BIAS);
        for (int i = t; i < 64; i += nt) {
            bias[i] = mb0[i]; bias[64 + i] = mb1[i]; bias[128 + i] = mb2[i];
        }
        for (int i = t; i < 128; i += nt) {
            bias[192 + i] = mb3[i]; bias[320 + i] = mb4[i];
        }
    }

    if (tid < 128) g_feat[bp * 128 + tid] = 0.f;

    float sx = g_seed[bp * 3 + 0], sy = g_seed[bp * 3 + 1], sz = g_seed[bp * 3 + 2];
    float s2 = sx * sx + sy * sy + sz * sz;

    for (int i = tid; i < NN; i += 512) {
        float px = X[i], py = X[NN + i], pz = X[2 * NN + i];
        float p2 = px * px + py * py + pz * pz;
        float dot = sx * px + sy * py + sz * pz;
        float d = (s2 - 2.0f * dot) + p2;
        unsigned u = __float_as_uint(d);
        u = (u & 0x80000000u) ? ~u : (u | 0x80000000u);
        s_key[i] = u;
    }
    if (tid == 0) { s_pref = 0u; s_kk = SS; }
    __syncthreads();

    unsigned prefix = 0, maskHi = 0;
    int bank = ((tid >> 5) & 1) * 256;
    for (int pass = 0; pass < 4; pass++) {
        int shift = 24 - 8 * pass;
        s_hist[tid] = 0;
        __syncthreads();
        for (int i = tid; i < NN; i += 512) {
            unsigned u = s_key[i];
            if ((u & maskHi) == prefix) atomicAdd(&s_hist[bank + ((u >> shift) & 255)], 1);
        }
        __syncthreads();
        if (tid < 32) {
            int kk = s_kk;
            unsigned pref = s_pref;
            int sv[8]; int tot = 0;
#pragma unroll
            for (int j = 0; j < 8; j++) {
                int v = s_hist[lane * 8 + j] + s_hist[256 + lane * 8 + j];
                sv[j] = v; tot += v;
            }
            int run = tot;
#pragma unroll
            for (int o = 1; o < 32; o <<= 1) {
                int v = __shfl_up_sync(0xffffffffu, run, o);
                if (lane >= o) run += v;
            }
            int excl = run - tot;
            if (kk > excl && kk <= run) {
                int cum = excl;
#pragma unroll
                for (int j = 0; j < 8; j++) {
                    if (cum + sv[j] >= kk) {
                        s_pref = pref | ((unsigned)(lane * 8 + j) << shift);
                        s_kk = kk - cum;
                        break;
                    }
                    cum += sv[j];
                }
            }
        }
        __syncthreads();
        prefix = s_pref;
        maskHi |= (0xFFu << shift);
        __syncthreads();
    }
    unsigned T = prefix;

    if (tid == 0) { s_cnt[0] = 0; s_cnt[1] = 0; }
    __syncthreads();
    for (int i = tid; i < NN; i += 512) {
        bool pred = s_key[i] < T;
        unsigned m = __ballot_sync(0xffffffffu, pred);
        int cnt = __popc(m);
        int base = 0;
        if (lane == 0 && cnt) base = atomicAdd(&s_cnt[0], cnt);
        base = __shfl_sync(0xffffffffu, base, 0);
        if (pred) s_sel[base + __popc(m & ((1u << lane) - 1u))] = i;
    }
    __syncthreads();
    int nLess = s_cnt[0];
    for (int i = tid; i < NN; i += 512) {
        bool pred = s_key[i] == T;
        unsigned m = __ballot_sync(0xffffffffu, pred);
        int cnt = __popc(m);
        int base = 0;
        if (lane == 0 && cnt) base = atomicAdd(&s_cnt[1], cnt);
        base = __shfl_sync(0xffffffffu, base, 0);
        if (pred) {
            int pos = nLess + base + __popc(m & ((1u << lane) - 1u));
            if (pos < SS) s_sel[pos] = i;
        }
    }
    __syncthreads();

    float* cxs = (float*)s_key;
    float* cys = cxs + SS;
    float* czs = cxs + 2 * SS;
    float ax = 0.f, ay = 0.f, az = 0.f;
    for (int j = tid; j < SS; j += 512) {
        int i = s_sel[j];
        float px = X[i], py = X[NN + i], pz = X[2 * NN + i];
        cxs[j] = px; cys[j] = py; czs[j] = pz;
        ax += px; ay += py; az += pz;
    }
    s_red[tid] = ax; __syncthreads();
    for (int s = 256; s > 0; s >>= 1) { if (tid < s) s_red[tid] += s_red[tid + s]; __syncthreads(); }
    float mx = s_red[0] * (1.0f / SS); __syncthreads();
    s_red[tid] = ay; __syncthreads();
    for (int s = 256; s > 0; s >>= 1) { if (tid < s) s_red[tid] += s_red[tid + s]; __syncthreads(); }
    float my = s_red[0] * (1.0f / SS); __syncthreads();
    s_red[tid] = az; __syncthreads();
    for (int s = 256; s > 0; s >>= 1) { if (tid < s) s_red[tid] += s_red[tid + s]; __syncthreads(); }
    float mz = s_red[0] * (1.0f / SS); __syncthreads();

    float mnorm = 0.f;
    for (int j = tid; j < SS; j += 512) {
        float dx = cxs[j] - mx, dy = cys[j] - my, dz = czs[j] - mz;
        float l = sqrtf(dx * dx + dy * dy + dz * dz);
        mnorm = fmaxf(mnorm, l);
    }
    s_red[tid] = mnorm; __syncthreads();
    for (int s = 256; s > 0; s >>= 1) { if (tid < s) s_red[tid] = fmaxf(s_red[tid], s_red[tid + s]); __syncthreads(); }
    float nrm = s_red[0]; __syncthreads();

    for (int j = tid; j < SS; j += 512) {
        g_patch[(bp * 3 + 0) * SS + j] = (cxs[j] - mx) / nrm;
        g_patch[(bp * 3 + 1) * SS + j] = (cys[j] - my) / nrm;
        g_patch[(bp * 3 + 2) * SS + j] = (czs[j] - mz) / nrm;
    }
    if (tid == 0) {
        g_mean[bp * 3 + 0] = mx; g_mean[bp * 3 + 1] = my; g_mean[bp * 3 + 2] = mz;
        g_norm[bp] = nrm;
    }
}

// =========================================================================
// Kernel 3: fused MLP — EXACT Round-9 configuration (best measured: 263.3us).
// =========================================================================
template<int KC, int NT, int STRIDE>
__device__ __forceinline__ void layer_forward2(
    const uint32_t (*Ah0)[4], const uint32_t (*Al0)[4],
    const uint32_t (*Ah1)[4], const uint32_t (*Al1)[4],
    uint32_t wH, uint32_t wL, const float* __restrict__ bias, int lane,
    uint32_t (*Oh0)[4], uint32_t (*Ol0)[4],
    uint32_t (*Oh1)[4], uint32_t (*Ol1)[4]) {
    uint32_t lm = (uint32_t)(lane & 7) * STRIDE + (uint32_t)((lane >> 3) & 1) * 16;
    int t4 = lane & 3;
#pragma unroll
    for (int np = 0; np < NT / 2; np++) {
        float ccA[2][4], ccB[2][4];
#pragma unroll
        for (int sub = 0; sub < 2; sub++) {
            int nt = np * 2 + sub;
            uint32_t ro = lm + (uint32_t)nt * 8u * STRIDE;
            float c1a[4] = {0.f, 0.f, 0.f, 0.f}, c2a[4] = {0.f, 0.f, 0.f, 0.f};
            float c1b[4] = {0.f, 0.f, 0.f, 0.f}, c2b[4] = {0.f, 0.f, 0.f, 0.f};
#pragma unroll
            for (int kc = 0; kc < KC; kc++) {
                uint32_t b0, b1, l0, l1;
                ldm_x2(b0, b1, wH + ro + kc * 32);
                ldm_x2(l0, l1, wL + ro + kc * 32);
                mma_bf16(c1a, Ah0[kc], b0, b1);
                mma_bf16(c1b, Ah1[kc], b0, b1);
                mma_bf16(c2a, Ah0[kc], l0, l1);
                mma_bf16(c2b, Ah1[kc], l0, l1);
                mma_bf16(c2a, Al0[kc], b0, b1);
                mma_bf16(c2b, Al1[kc], b0, b1);
            }
            float2 bb = *reinterpret_cast<const float2*>(bias + nt * 8 + t4 * 2);
            ccA[sub][0] = fmaxf(c1a[0] + c2a[0] + bb.x, 0.f);
            ccA[sub][1] = fmaxf(c1a[1] + c2a[1] + bb.y, 0.f);
            ccA[sub][2] = fmaxf(c1a[2] + c2a[2] + bb.x, 0.f);
            ccA[sub][3] = fmaxf(c1a[3] + c2a[3] + bb.y, 0.f);
            ccB[sub][0] = fmaxf(c1b[0] + c2b[0] + bb.x, 0.f);
            ccB[sub][1] = fmaxf(c1b[1] + c2b[1] + bb.y, 0.f);
            ccB[sub][2] = fmaxf(c1b[2] + c2b[2] + bb.x, 0.f);
            ccB[sub][3] = fmaxf(c1b[3] + c2b[3] + bb.y, 0.f);
        }
        split2(ccA[0][0], ccA[0][1], Oh0[np][0], Ol0[np][0]);
        split2(ccA[0][2], ccA[0][3], Oh0[np][1], Ol0[np][1]);
        split2(ccA[1][0], ccA[1][1], Oh0[np][2], Ol0[np][2]);
        split2(ccA[1][2], ccA[1][3], Oh0[np][3], Ol0[np][3]);
        split2(ccB[0][0], ccB[0][1], Oh1[np][0], Ol1[np][0]);
        split2(ccB[0][2], ccB[0][3], Oh1[np][1], Ol1[np][1]);
        split2(ccB[1][0], ccB[1][1], Oh1[np][2], Ol1[np][2]);
        split2(ccB[1][2], ccB[1][3], Oh1[np][3], Ol1[np][3]);
    }
}

template<int KC, int NT, int STRIDE>
__device__ __forceinline__ void layer_final2(
    const uint32_t (*Ah0)[4], const uint32_t (*Al0)[4],
    const uint32_t (*Ah1)[4], const uint32_t (*Al1)[4],
    uint32_t wH, uint32_t wL, const float* __restrict__ bias, int lane, int* smax) {
    uint32_t lm = (uint32_t)(lane & 7) * STRIDE + (uint32_t)((lane >> 3) & 1) * 16;
    int t4 = lane & 3;
#pragma unroll
    for (int nt = 0; nt < NT; nt++) {
        uint32_t ro = lm + (uint32_t)nt * 8u * STRIDE;
        float c1a[4] = {0.f, 0.f, 0.f, 0.f}, c2a[4] = {0.f, 0.f, 0.f, 0.f};
        float c1b[4] = {0.f, 0.f, 0.f, 0.f}, c2b[4] = {0.f, 0.f, 0.f, 0.f};
#pragma unroll
        for (int kc = 0; kc < KC; kc++) {
            uint32_t b0, b1, l0, l1;
            ldm_x2(b0, b1, wH + ro + kc * 32);
            ldm_x2(l0, l1, wL + ro + kc * 32);
            mma_bf16(c1a, Ah0[kc], b0, b1);
            mma_bf16(c1b, Ah1[kc], b0, b1);
            mma_bf16(c2a, Ah0[kc], l0, l1);
            mma_bf16(c2b, Ah1[kc], l0, l1);
            mma_bf16(c2a, Al0[kc], b0, b1);
            mma_bf16(c2b, Al1[kc], b0, b1);
        }
        float2 bb = *reinterpret_cast<const float2*>(bias + nt * 8 + t4 * 2);
        float v0a = fmaxf(c1a[0] + c2a[0] + bb.x, 0.f), v2a = fmaxf(c1a[2] + c2a[2] + bb.x, 0.f);
        float v1a = fmaxf(c1a[1] + c2a[1] + bb.y, 0.f), v3a = fmaxf(c1a[3] + c2a[3] + bb.y, 0.f);
        float v0b = fmaxf(c1b[0] + c2b[0] + bb.x, 0.f), v2b = fmaxf(c1b[2] + c2b[2] + bb.x, 0.f);
        float v1b = fmaxf(c1b[1] + c2b[1] + bb.y, 0.f), v3b = fmaxf(c1b[3] + c2b[3] + bb.y, 0.f);
        float m0 = fmaxf(fmaxf(v0a, v2a), fmaxf(v0b, v2b));
        float m1 = fmaxf(fmaxf(v1a, v3a), fmaxf(v1b, v3b));
#pragma unroll
        for (int off = 4; off < 32; off <<= 1) {
            m0 = fmaxf(m0, __shfl_xor_sync(0xffffffffu, m0, off));
            m1 = fmaxf(m1, __shfl_xor_sync(0xffffffffu, m1, off));
        }
        if (lane < 4) {
            atomicMax(&smax[nt * 8 + 2 * lane], __float_as_int(m0));
            atomicMax(&smax[nt * 8 + 2 * lane + 1], __float_as_int(m1));
        }
    }
}

__global__ void __launch_bounds__(256, 1) mlp_mma_kernel() {
    extern __shared__ char sm[];
    __shared__ int smax[128];
    int bp2 = blockIdx.x;
    int bp = bp2 >> 1;
    int half = bp2 & 1;
    int tid = threadIdx.x;
    int lane = tid & 31;
    int w = tid >> 5;
    uint32_t sbase = smem_to_u32(sm);

    if (tid < 128) smax[tid] = 0;
    {
        const uint4* src = (const uint4*)g_wbuf;
        uint4* dst = (uint4*)sm;
        for (int i = tid; i < DYN_TOT / 16; i += 256) dst[i] = src[i];
    }
    __syncthreads();

    const float* sbias = (const float*)(sm + O_BIAS);
    const float* PX = &g_patch[(bp * 3 + 0) * SS];
    const float* PY = &g_patch[(bp * 3 + 1) * SS];
    const float* PZ = &g_patch[(bp * 3 + 2) * SS];
    int t4 = lane & 3;

    for (int it = 0; it < 2; it++) {
        int pbase = half * 512 + it * 256 + w * 32 + (lane >> 2);
        float x0 = PX[pbase], y0 = PY[pbase], z0 = PZ[pbase];
        float x1 = PX[pbase + 8], y1 = PY[pbase + 8], z1 = PZ[pbase + 8];
        float x2 = PX[pbase + 16], y2 = PY[pbase + 16], z2 = PZ[pbase + 16];
        float x3 = PX[pbase + 24], y3 = PY[pbase + 24], z3 = PZ[pbase + 24];

        uint32_t A1h0[1][4] = {{0u, 0u, 0u, 0u}}, A1l0[1][4] = {{0u, 0u, 0u, 0u}};
        uint32_t A1h1[1][4] = {{0u, 0u, 0u, 0u}}, A1l1[1][4] = {{0u, 0u, 0u, 0u}};
        if (t4 == 0) {
            split2(x0, y0, A1h0[0][0], A1l0[0][0]);
            split2(x1, y1, A1h0[0][1], A1l0[0][1]);
            split2(x2, y2, A1h1[0][0], A1l1[0][0]);
            split2(x3, y3, A1h1[0][1], A1l1[0][1]);
        } else if (t4 == 1) {
            split2(z0, 0.f, A1h0[0][0], A1l0[0][0]);
            split2(z1, 0.f, A1h0[0][1], A1l0[0][1]);
            split2(z2, 0.f, A1h1[0][0], A1l1[0][0]);
            split2(z3, 0.f, A1h1[0][1], A1l1[0][1]);
        }

        uint32_t A2h0[4][4], A2l0[4][4], A2h1[4][4], A2l1[4][4];
        uint32_t A3h0[4][4], A3l0[4][4], A3h1[4][4], A3l1[4][4];
        uint32_t A4h0[4][4], A4l0[4][4], A4h1[4][4], A4l1[4][4];
        uint32_t A5h0[8][4], A5l0[8][4], A5h1[8][4], A5l1[8][4];

        layer_forward2<1, 8, 48>(A1h0, A1l0, A1h1, A1l1,
            sbase + O_W1H, sbase + O_W1L, sbias + 0, lane,
            A2h0, A2l0, A2h1, A2l1);
        layer_forward2<4, 8, 144>(A2h0, A2l0, A2h1, A2l1,
            sbase + O_W2H, sbase + O_W2L, sbias + 64, lane,
            A3h0, A3l0, A3h1, A3l1);
        layer_forward2<4, 8, 144>(A3h0, A3l0, A3h1, A3l1,
            sbase + O_W3H, sbase + O_W3L, sbias + 128, lane,
            A4h0, A4l0, A4h1, A4l1);
        layer_forward2<4, 16, 144>(A4h0, A4l0, A4h1, A4l1,
            sbase + O_W4H, sbase + O_W4L, sbias + 192, lane,
            A5h0, A5l0, A5h1, A5l1);
        layer_final2<8, 16, 272>(A5h0, A5l0, A5h1, A5l1,
            sbase + O_W5H, sbase + O_W5L, sbias + 320, lane, smax);
    }
    __syncthreads();
    if (tid < 128) atomicMax((int*)&g_feat[bp * 128 + tid], smax[tid]);
}

// =========================================================================
// Kernel 4: FUSED FC decoder + SoftProjection (proven, round 14).
// =========================================================================
__global__ void __launch_bounds__(1024) dec_proj_kernel(
    const float* __restrict__ fw0, const float* __restrict__ fb0,
    const float* __restrict__ fw1, const float* __restrict__ fb1,
    const float* __restrict__ fw2, const float* __restrict__ fb2,
    const float* __restrict__ fw3, const float* __restrict__ fb3,
    const float* __restrict__ temperature,
    float* __restrict__ out) {
    int pbase = blockIdx.x * 4;
    int tid = threadIdx.x;
    int c = tid & 255;
    int q = tid >> 8;            // k-quarter 0..3
    __shared__ float sA[4][256];
    __shared__ float sB[4][256];
    __shared__ float sP[3][4][256];
    __shared__ float s_gen[4][24];

    if (tid < 512) {
        int p = tid >> 7, cc = tid & 127;
        sA[p][cc] = g_feat[(pbase + p) * 128 + cc];
    }
    __syncthreads();

    {
        float acc[4] = {0.f, 0.f, 0.f, 0.f};
        const float* W = fw0 + (q * 32) * 256 + c;
#pragma unroll 8
        for (int k = 0; k < 32; k++) {
            float wv = W[k * 256];
#pragma unroll
            for (int p = 0; p < 4; p++) acc[p] = fmaf(sA[p][q * 32 + k], wv, acc[p]);
        }
        if (q > 0) {
#pragma unroll
            for (int p = 0; p < 4; p++) sP[q - 1][p][c] = acc[p];
        }
        __syncthreads();
        if (q == 0) {
            float bv = fb0[c];
#pragma unroll
            for (int p = 0; p < 4; p++)
                sB[p][c] = fmaxf(acc[p] + sP[0][p][c] + sP[1][p][c] + sP[2][p][c] + bv, 0.f);
        }
        __syncthreads();
    }
    {
        float acc[4] = {0.f, 0.f, 0.f, 0.f};
        const float* W = fw1 + (q * 64) * 256 + c;
#pragma unroll 8
        for (int k = 0; k < 64; k++) {
            float wv = W[k * 256];
#pragma unroll
            for (int p = 0; p < 4; p++) acc[p] = fmaf(sB[p][q * 64 + k], wv, acc[p]);
        }
        if (q > 0) {
#pragma unroll
            for (int p = 0; p < 4; p++) sP[q - 1][p][c] = acc[p];
        }
        __syncthreads();
        if (q == 0) {
            float bv = fb1[c];
#pragma unroll
            for (int p = 0; p < 4; p++)
                sA[p][c] = fmaxf(acc[p] + sP[0][p][c] + sP[1][p][c] + sP[2][p][c] + bv, 0.f);
        }
        __syncthreads();
    }
    {
        float acc[4] = {0.f, 0.f, 0.f, 0.f};
        const float* W = fw2 + (q * 64) * 256 + c;
#pragma unroll 8
        for (int k = 0; k < 64; k++) {
            float wv = W[k * 256];
#pragma unroll
            for (int p = 0; p < 4; p++) acc[p] = fmaf(sA[p][q * 64 + k], wv, acc[p]);
        }
        if (q > 0) {
#pragma unroll
            for (int p = 0; p < 4; p++) sP[q - 1][p][c] = acc[p];
        }
        __syncthreads();
        if (q == 0) {
            float bv = fb2[c];
#pragma unroll
            for (int p = 0; p < 4; p++)
                sB[p][c] = fmaxf(acc[p] + sP[0][p][c] + sP[1][p][c] + sP[2][p][c] + bv, 0.f);
        }
        __syncthreads();
    }
    {
        float acc = 0.f;
        int p = 0, o = 0, qq = 0;
        bool act = (tid < 384);
        if (act) {
            p = tid / 96;
            int r = tid % 96;
            o = r % 24;
            qq = r / 24;
            const float* W = fw3 + (qq * 64) * 24 + o;
#pragma unroll 8
            for (int k = 0; k < 64; k++)
                acc = fmaf(sB[p][qq * 64 + k], W[k * 24], acc);
            if (qq > 0) sP[qq - 1][p][o] = acc;
        }
        __syncthreads();
        if (act && qq == 0)
            s_gen[p][o] = acc + sP[0][p][o] + sP[1][p][o] + sP[2][p][o] + fb3[o];
    }
    __syncthreads();

    // ---- Phase 2: SoftProjection ----
    {
        int wrp = tid >> 5;          // 0..31
        int lane = tid & 31;
        int p = wrp >> 3;
        int m = wrp & 7;
        int bp = pbase + p;
        float t = temperature[0];
        float sigma = fmaxf(t * t, 1e-4f);

        const float* PX = &g_patch[(bp * 3 + 0) * SS];
        const float* PY = &g_patch[(bp * 3 + 1) * SS];
        const float* PZ = &g_patch[(bp * 3 + 2) * SS];

        float qx = s_gen[p][m * 3 + 0];
        float qy = s_gen[p][m * 3 + 1];
        float qz = s_gen[p][m * 3 + 2];
        float q2 = qx * qx + qy * qy + qz * qz;

        float bd[7]; int bi[7];
#pragma unroll
        for (int k = 0; k < 7; k++) { bd[k] = 3.4e38f; bi[k] = 0; }

        for (int i = lane; i < SS; i += 32) {
            float px = PX[i], py = PY[i], pz = PZ[i];
            float p2 = px * px + py * py + pz * pz;
            float dot = qx * px + qy * py + qz * pz;
            float d = (q2 - 2.0f * dot) + p2;
            if (d < bd[6]) {
                bd[6] = d; bi[6] = i;
#pragma unroll
                for (int k = 6; k > 0; k--) {
                    if (bd[k] < bd[k - 1]) {
                        float td = bd[k]; bd[k] = bd[k - 1]; bd[k - 1] = td;
                        int ti = bi[k]; bi[k] = bi[k - 1]; bi[k - 1] = ti;
                    }
                }
            }
        }
        float selD[7]; int selI[7];
#pragma unroll
        for (int k = 0; k < 7; k++) {
            float mv = bd[0]; int ml = lane;
#pragma unroll
            for (int o = 16; o > 0; o >>= 1) {
                float ov = __shfl_xor_sync(0xffffffffu, mv, o);
                int ol = __shfl_xor_sync(0xffffffffu, ml, o);
                if (ov < mv || (ov == mv && ol < ml)) { mv = ov; ml = ol; }
            }
            selD[k] = mv;
            selI[k] = __shfl_sync(0xffffffffu, bi[0], ml);
            if (lane == ml) {
#pragma unroll
                for (int qd = 0; qd < 6; qd++) { bd[qd] = bd[qd + 1]; bi[qd] = bi[qd + 1]; }
                bd[6] = 3.4e38f;
            }
        }
        if (lane == 0) {
            float wsum = 0.f, sx = 0.f, sy = 0.f, sz = 0.f;
#pragma unroll
            for (int k = 0; k < 7; k++) {
                float wgt = expf((selD[0] - selD[k]) / sigma);
                int i = selI[k];
                wsum += wgt;
                sx = fmaf(wgt, PX[i], sx);
                sy = fmaf(wgt, PY[i], sy);
                sz = fmaf(wgt, PZ[i], sz);
            }
            float inv = 1.0f / wsum;
            float nrm = g_norm[bp];
            float mex = g_mean[bp * 3 + 0], mey = g_mean[bp * 3 + 1], mez = g_mean[bp * 3 + 2];
            int o = (bp * MM + m) * 3;
            out[o + 0] = fmaf(sx * inv, nrm, mex);
            out[o + 1] = fmaf(sy * inv, nrm, mey);
            out[o + 2] = fmaf(sz * inv, nrm, mez);
        }
    }
}

// =========================================================================
extern "C" void kernel_launch(void* const* d_in, const int* in_sizes, int n_in,
                              void* d_out, int out_size) {
    const float* xyz = (const float*)d_in[0];
    const float* mw0 = (const float*)d_in[1];  const float* mb0 = (const float*)d_in[2];
    const float* mw1 = (const float*)d_in[3];  const float* mb1 = (const float*)d_in[4];
    const float* mw2 = (const float*)d_in[5];  const float* mb2 = (const float*)d_in[6];
    const float* mw3 = (const float*)d_in[7];  const float* mb3 = (const float*)d_in[8];
    const float* mw4 = (const float*)d_in[9];  const float* mb4 = (const float*)d_in[10];
    const float* fw0 = (const float*)d_in[11]; const float* fb0 = (const float*)d_in[12];
    const float* fw1 = (const float*)d_in[13]; const float* fb1 = (const float*)d_in[14];
    const float* fw2 = (const float*)d_in[15]; const float* fb2 = (const float*)d_in[16];
    const float* fw3 = (const float*)d_in[17]; const float* fb3 = (const float*)d_in[18];
    const float* temp = (const float*)d_in[19];
    float* out = (float*)d_out;

    cudaFuncSetAttribute(mlp_mma_kernel, cudaFuncAttributeMaxDynamicSharedMemorySize,
                         DYN_TOT);

    fps_kernel<<<BB, 1024>>>(xyz);
    knn_kernel<<<NPATCH, 512>>>(xyz, mw0, mb0, mw1, mb1, mw2, mb2,
                                mw3, mb3, mw4, mb4);
    mlp_mma_kernel<<<NPATCH * 2, 256, DYN_TOT>>>();
    dec_proj_kernel<<<128, 1024>>>(fw0, fb0, fw1, fb1, fw2, fb2, fw3, fb3,
                                   temp, out);
}